// round 2
// baseline (speedup 1.0000x reference)
#include <cuda_runtime.h>
#include <math.h>

#define B_  2
#define S_  2048
#define D_  1024
#define H_  16
#define DH_ 64
#define M_  (B_ * S_)          // 4096 rows total
#define NEGV (-4294967295.0f)  // -2^32 + 1

// ---------------- scratch (static device globals; no allocations) ----------
__device__ float g_Q[M_ * D_];
__device__ float g_K[M_ * D_];
__device__ float g_V[M_ * D_];
__device__ float g_O[M_ * D_];
__device__ float g_kmask[M_];
__device__ float g_qmask[M_];

// ---------------- fused QKV projection: out = relu(X @ W^T + b) ------------
// M=4096, N=1024, K=1024.  BM=BN=128, BK=16, 256 threads, 8x8 per thread.
__global__ __launch_bounds__(256) void proj_kernel(
    const float* __restrict__ Xq, const float* __restrict__ Xk, const float* __restrict__ Xv,
    const float* __restrict__ Wq, const float* __restrict__ Wk, const float* __restrict__ Wv,
    const float* __restrict__ bq, const float* __restrict__ bk, const float* __restrict__ bv)
{
    __shared__ float As[16][132];
    __shared__ float Bs[16][132];

    const float* X;  const float* W;  const float* bias;  float* out;
    if (blockIdx.z == 0)      { X = Xq; W = Wq; bias = bq; out = g_Q; }
    else if (blockIdx.z == 1) { X = Xk; W = Wk; bias = bk; out = g_K; }
    else                      { X = Xv; W = Wv; bias = bv; out = g_V; }

    const int tid = threadIdx.x;
    const int m0  = blockIdx.y * 128;
    const int n0  = blockIdx.x * 128;
    const int tx  = tid & 15;
    const int ty  = tid >> 4;

    float acc[8][8];
    #pragma unroll
    for (int i = 0; i < 8; i++)
        #pragma unroll
        for (int j = 0; j < 8; j++) acc[i][j] = 0.0f;

    for (int k0 = 0; k0 < 1024; k0 += 16) {
        // cooperative load, transposed into smem
        #pragma unroll
        for (int lv = 0; lv < 2; lv++) {
            int idx = tid + lv * 256;          // 0..511 float4 slots
            int row = idx >> 2;
            int c4  = (idx & 3) * 4;
            float4 a = *(const float4*)&X[(size_t)(m0 + row) * D_ + k0 + c4];
            As[c4 + 0][row] = a.x; As[c4 + 1][row] = a.y;
            As[c4 + 2][row] = a.z; As[c4 + 3][row] = a.w;
            float4 w = *(const float4*)&W[(size_t)(n0 + row) * D_ + k0 + c4];
            Bs[c4 + 0][row] = w.x; Bs[c4 + 1][row] = w.y;
            Bs[c4 + 2][row] = w.z; Bs[c4 + 3][row] = w.w;
        }
        __syncthreads();

        #pragma unroll
        for (int kk = 0; kk < 16; kk++) {
            float a[8], b[8];
            *(float4*)&a[0] = *(const float4*)&As[kk][ty * 8];
            *(float4*)&a[4] = *(const float4*)&As[kk][ty * 8 + 4];
            *(float4*)&b[0] = *(const float4*)&Bs[kk][tx * 8];
            *(float4*)&b[4] = *(const float4*)&Bs[kk][tx * 8 + 4];
            #pragma unroll
            for (int i = 0; i < 8; i++)
                #pragma unroll
                for (int j = 0; j < 8; j++)
                    acc[i][j] += a[i] * b[j];
        }
        __syncthreads();
    }

    // epilogue: bias + relu
    #pragma unroll
    for (int i = 0; i < 8; i++) {
        int m = m0 + ty * 8 + i;
        #pragma unroll
        for (int j = 0; j < 8; j += 4) {
            int n = n0 + tx * 8 + j;
            float4 r;
            r.x = fmaxf(acc[i][j + 0] + bias[n + 0], 0.0f);
            r.y = fmaxf(acc[i][j + 1] + bias[n + 1], 0.0f);
            r.z = fmaxf(acc[i][j + 2] + bias[n + 2], 0.0f);
            r.w = fmaxf(acc[i][j + 3] + bias[n + 3], 0.0f);
            *(float4*)&out[(size_t)m * D_ + n] = r;
        }
    }
}

// ---------------- padding masks from raw inputs ----------------------------
__global__ __launch_bounds__(256) void mask_kernel(
    const float* __restrict__ queries, const float* __restrict__ keys)
{
    __shared__ float rq[8];
    __shared__ float rk[8];
    const int row = blockIdx.x;
    const int tid = threadIdx.x;
    size_t base = (size_t)row * D_ + tid * 4;
    float4 q = *(const float4*)&queries[base];
    float4 k = *(const float4*)&keys[base];
    float sq = q.x + q.y + q.z + q.w;
    float sk = k.x + k.y + k.z + k.w;
    #pragma unroll
    for (int o = 16; o; o >>= 1) {
        sq += __shfl_xor_sync(0xffffffffu, sq, o);
        sk += __shfl_xor_sync(0xffffffffu, sk, o);
    }
    if ((tid & 31) == 0) { rq[tid >> 5] = sq; rk[tid >> 5] = sk; }
    __syncthreads();
    if (tid == 0) {
        float tq = 0.f, tk = 0.f;
        #pragma unroll
        for (int i = 0; i < 8; i++) { tq += rq[i]; tk += rk[i]; }
        g_qmask[row] = (tq != 0.0f) ? 1.0f : 0.0f;
        g_kmask[row] = (tk != 0.0f) ? 1.0f : 0.0f;
    }
}

// ---------------- causal flash attention (fp32) -----------------------------
// Block: 64 q-rows of one (b, h).  256 threads in 16x16 grid, 4x4 per thread.
#define PITCH 68
__global__ __launch_bounds__(256) void attn_kernel()
{
    extern __shared__ float sm[];
    float* Qs = sm;
    float* Ks = sm + 64 * PITCH;
    float* Vs = sm + 2 * 64 * PITCH;
    float* Ps = sm + 3 * 64 * PITCH;

    const int qt  = blockIdx.x;          // 0..31
    const int h   = blockIdx.y;          // 0..15
    const int b   = blockIdx.z;          // 0..1
    const int tid = threadIdx.x;
    const int tx  = tid & 15;
    const int ty  = tid >> 4;
    const int q0  = qt * 64;
    const int r0  = ty * 4;
    const int c0  = tx * 4;

    // load Q tile
    #pragma unroll
    for (int lv = 0; lv < 4; lv++) {
        int idx = tid + lv * 256;            // 0..1023 float4 slots
        int r = idx >> 4;
        int d = (idx & 15) * 4;
        *(float4*)&Qs[r * PITCH + d] =
            *(const float4*)&g_Q[(size_t)(b * S_ + q0 + r) * D_ + h * DH_ + d];
    }

    float m[4], l[4], O[4][4];
    #pragma unroll
    for (int i = 0; i < 4; i++) {
        m[i] = -1e30f; l[i] = 0.0f;
        #pragma unroll
        for (int j = 0; j < 4; j++) O[i][j] = 0.0f;
    }

    for (int kt = 0; kt <= qt; kt++) {
        __syncthreads();                     // protect smem reuse
        const int s0 = kt * 64;
        #pragma unroll
        for (int lv = 0; lv < 4; lv++) {
            int idx = tid + lv * 256;
            int r = idx >> 4;
            int d = (idx & 15) * 4;
            size_t base = (size_t)(b * S_ + s0 + r) * D_ + h * DH_ + d;
            *(float4*)&Ks[r * PITCH + d] = *(const float4*)&g_K[base];
            *(float4*)&Vs[r * PITCH + d] = *(const float4*)&g_V[base];
        }
        __syncthreads();

        // S = Q K^T
        float s[4][4];
        #pragma unroll
        for (int i = 0; i < 4; i++)
            #pragma unroll
            for (int j = 0; j < 4; j++) s[i][j] = 0.0f;

        #pragma unroll
        for (int d = 0; d < 64; d += 4) {
            float4 qv[4], kv[4];
            #pragma unroll
            for (int i = 0; i < 4; i++) qv[i] = *(const float4*)&Qs[(r0 + i) * PITCH + d];
            #pragma unroll
            for (int j = 0; j < 4; j++) kv[j] = *(const float4*)&Ks[(c0 + j) * PITCH + d];
            #pragma unroll
            for (int i = 0; i < 4; i++)
                #pragma unroll
                for (int j = 0; j < 4; j++)
                    s[i][j] += qv[i].x * kv[j].x + qv[i].y * kv[j].y +
                               qv[i].z * kv[j].z + qv[i].w * kv[j].w;
        }

        // masks: causal + key padding
        float km[4];
        #pragma unroll
        for (int j = 0; j < 4; j++) km[j] = g_kmask[b * S_ + s0 + c0 + j];
        #pragma unroll
        for (int i = 0; i < 4; i++) {
            int qg = q0 + r0 + i;
            #pragma unroll
            for (int j = 0; j < 4; j++) {
                int kg = s0 + c0 + j;
                float v = s[i][j] * 0.125f;
                s[i][j] = (kg > qg || km[j] == 0.0f) ? NEGV : v;
            }
        }

        // online softmax (rows reduced over the 16 tx lanes)
        #pragma unroll
        for (int i = 0; i < 4; i++) {
            float mloc = fmaxf(fmaxf(s[i][0], s[i][1]), fmaxf(s[i][2], s[i][3]));
            #pragma unroll
            for (int o = 8; o >= 1; o >>= 1)
                mloc = fmaxf(mloc, __shfl_xor_sync(0xffffffffu, mloc, o));
            float mnew  = fmaxf(m[i], mloc);
            float alpha = __expf(m[i] - mnew);
            float psum  = 0.0f;
            #pragma unroll
            for (int j = 0; j < 4; j++) {
                float p = __expf(s[i][j] - mnew);
                Ps[(r0 + i) * PITCH + c0 + j] = p;
                psum += p;
            }
            #pragma unroll
            for (int o = 8; o >= 1; o >>= 1)
                psum += __shfl_xor_sync(0xffffffffu, psum, o);
            l[i] = l[i] * alpha + psum;
            m[i] = mnew;
            #pragma unroll
            for (int j = 0; j < 4; j++) O[i][j] *= alpha;
        }
        __syncthreads();

        // O += P @ V
        #pragma unroll
        for (int j = 0; j < 64; j += 4) {
            float4 pv[4], vv[4];
            #pragma unroll
            for (int i = 0; i < 4; i++) pv[i] = *(const float4*)&Ps[(r0 + i) * PITCH + j];
            #pragma unroll
            for (int jj = 0; jj < 4; jj++) vv[jj] = *(const float4*)&Vs[(j + jj) * PITCH + c0];
            #pragma unroll
            for (int i = 0; i < 4; i++) {
                O[i][0] += pv[i].x * vv[0].x + pv[i].y * vv[1].x + pv[i].z * vv[2].x + pv[i].w * vv[3].x;
                O[i][1] += pv[i].x * vv[0].y + pv[i].y * vv[1].y + pv[i].z * vv[2].y + pv[i].w * vv[3].y;
                O[i][2] += pv[i].x * vv[0].z + pv[i].y * vv[1].z + pv[i].z * vv[2].z + pv[i].w * vv[3].z;
                O[i][3] += pv[i].x * vv[0].w + pv[i].y * vv[1].w + pv[i].z * vv[2].w + pv[i].w * vv[3].w;
            }
        }
    }

    // epilogue: normalize, apply query mask, store
    #pragma unroll
    for (int i = 0; i < 4; i++) {
        int qg = q0 + r0 + i;
        float qm  = g_qmask[b * S_ + qg];
        float inv = qm / l[i];
        float4 o;
        o.x = O[i][0] * inv; o.y = O[i][1] * inv;
        o.z = O[i][2] * inv; o.w = O[i][3] * inv;
        *(float4*)&g_O[(size_t)(b * S_ + qg) * D_ + h * DH_ + c0] = o;
    }
}

// ---------------- residual + layernorm (unbiased std, eps on std) ----------
__global__ __launch_bounds__(256) void ln_kernel(
    const float* __restrict__ qin, const float* __restrict__ gamma,
    const float* __restrict__ beta, float* __restrict__ out)
{
    __shared__ float red[8];
    __shared__ float red2[8];
    const int row = blockIdx.x;
    const int tid = threadIdx.x;
    size_t base = (size_t)row * D_ + tid * 4;

    float4 o = *(const float4*)&g_O[base];
    float4 q = *(const float4*)&qin[base];
    float x0 = o.x + q.x, x1 = o.y + q.y, x2 = o.z + q.z, x3 = o.w + q.w;

    float s = x0 + x1 + x2 + x3;
    #pragma unroll
    for (int off = 16; off; off >>= 1) s += __shfl_xor_sync(0xffffffffu, s, off);
    if ((tid & 31) == 0) red[tid >> 5] = s;
    __syncthreads();
    float tot = red[0] + red[1] + red[2] + red[3] + red[4] + red[5] + red[6] + red[7];
    float mean = tot * (1.0f / 1024.0f);

    float d0 = x0 - mean, d1 = x1 - mean, d2 = x2 - mean, d3 = x3 - mean;
    float sq = d0 * d0 + d1 * d1 + d2 * d2 + d3 * d3;
    #pragma unroll
    for (int off = 16; off; off >>= 1) sq += __shfl_xor_sync(0xffffffffu, sq, off);
    if ((tid & 31) == 0) red2[tid >> 5] = sq;
    __syncthreads();
    float ssq = red2[0] + red2[1] + red2[2] + red2[3] + red2[4] + red2[5] + red2[6] + red2[7];
    float stdv = sqrtf(ssq / 1023.0f);
    float inv = 1.0f / (stdv + 1e-8f);

    float4 g = *(const float4*)&gamma[tid * 4];
    float4 be = *(const float4*)&beta[tid * 4];
    float4 y;
    y.x = g.x * d0 * inv + be.x;
    y.y = g.y * d1 * inv + be.y;
    y.z = g.z * d2 * inv + be.z;
    y.w = g.w * d3 * inv + be.w;
    *(float4*)&out[base] = y;
}

// ---------------- launch ----------------------------------------------------
extern "C" void kernel_launch(void* const* d_in, const int* in_sizes, int n_in,
                              void* d_out, int out_size)
{
    const float* queries = (const float*)d_in[0];
    const float* keys    = (const float*)d_in[1];
    const float* values  = (const float*)d_in[2];
    const float* Wq      = (const float*)d_in[3];
    const float* bq      = (const float*)d_in[4];
    const float* Wk      = (const float*)d_in[5];
    const float* bk      = (const float*)d_in[6];
    const float* Wv      = (const float*)d_in[7];
    const float* bv      = (const float*)d_in[8];
    const float* gamma   = (const float*)d_in[9];
    const float* beta    = (const float*)d_in[10];
    float* out = (float*)d_out;

    const int attn_smem = 4 * 64 * PITCH * sizeof(float);   // 69632 B
    cudaFuncSetAttribute(attn_kernel, cudaFuncAttributeMaxDynamicSharedMemorySize, attn_smem);

    proj_kernel<<<dim3(8, 32, 3), 256>>>(queries, keys, values, Wq, Wk, Wv, bq, bk, bv);
    mask_kernel<<<M_, 256>>>(queries, keys);
    attn_kernel<<<dim3(32, 16, 2), 256, attn_smem>>>();
    ln_kernel<<<M_, 256>>>(queries, gamma, beta, out);
}

// round 3
// speedup vs baseline: 3.4053x; 3.4053x over previous
#include <cuda_runtime.h>
#include <math.h>

#define B_  2
#define S_  2048
#define D_  1024
#define H_  16
#define DH_ 64
#define M_  (B_ * S_)
#define NEGV (-4294967295.0f)  // -2^32 + 1

// ---------------- scratch ----------------------------------------------------
__device__ float g_Q[M_ * D_];
__device__ float g_K[M_ * D_];
__device__ float g_V[M_ * D_];
__device__ float g_O[M_ * D_];
__device__ float g_kmask[M_];
__device__ float g_qmask[M_];

// ---------------- tf32 helpers ----------------------------------------------
__device__ __forceinline__ unsigned f2tf(float f) {
    unsigned u;
    asm("cvt.rna.tf32.f32 %0, %1;" : "=r"(u) : "f"(f));
    return u;
}
__device__ __forceinline__ void mma8(float* c,
                                     unsigned a0, unsigned a1, unsigned a2, unsigned a3,
                                     unsigned b0, unsigned b1) {
    asm volatile(
        "mma.sync.aligned.m16n8k8.row.col.f32.tf32.tf32.f32 "
        "{%0,%1,%2,%3},{%4,%5,%6,%7},{%8,%9},{%0,%1,%2,%3};"
        : "+f"(c[0]), "+f"(c[1]), "+f"(c[2]), "+f"(c[3])
        : "r"(a0), "r"(a1), "r"(a2), "r"(a3), "r"(b0), "r"(b1));
}

// ---------------- fused QKV projection: out = relu(X @ W^T + b), tf32 MMA ---
// M=4096, N=1024, K=1024. BM=BN=128, BK=16, 256 threads (8 warps, 2x4 grid),
// each warp computes 64x32 via 4x4 m16n8k8 tiles.
#define PP 20   // smem pitch (16 + 4) -> conflict-free fragment LDS
__global__ __launch_bounds__(256) void proj_kernel(
    const float* __restrict__ Xq, const float* __restrict__ Xk, const float* __restrict__ Xv,
    const float* __restrict__ Wq, const float* __restrict__ Wk, const float* __restrict__ Wv,
    const float* __restrict__ bq, const float* __restrict__ bk, const float* __restrict__ bv)
{
    __shared__ unsigned As[128 * PP];
    __shared__ unsigned Bs[128 * PP];

    const float* X; const float* W; const float* bias; float* out;
    if (blockIdx.z == 0)      { X = Xq; W = Wq; bias = bq; out = g_Q; }
    else if (blockIdx.z == 1) { X = Xk; W = Wk; bias = bk; out = g_K; }
    else                      { X = Xv; W = Wv; bias = bv; out = g_V; }

    const int tid  = threadIdx.x;
    const int m0   = blockIdx.y * 128;
    const int n0   = blockIdx.x * 128;
    const int wid  = tid >> 5;
    const int lane = tid & 31;
    const int g    = lane >> 2;
    const int tig  = lane & 3;
    const int wm   = (wid >> 2) * 64;   // 0 or 64
    const int wn   = (wid & 3) * 32;    // 0..96

    float acc[4][4][4];
    #pragma unroll
    for (int i = 0; i < 4; i++)
        #pragma unroll
        for (int j = 0; j < 4; j++)
            #pragma unroll
            for (int e = 0; e < 4; e++) acc[i][j][e] = 0.0f;

    for (int k0 = 0; k0 < 1024; k0 += 16) {
        #pragma unroll
        for (int lv = 0; lv < 2; lv++) {
            int idx = tid + lv * 256;        // 0..511 float4 slots
            int row = idx >> 2;
            int c4  = (idx & 3) * 4;
            float4 a = *(const float4*)&X[(size_t)(m0 + row) * D_ + k0 + c4];
            As[row * PP + c4 + 0] = f2tf(a.x); As[row * PP + c4 + 1] = f2tf(a.y);
            As[row * PP + c4 + 2] = f2tf(a.z); As[row * PP + c4 + 3] = f2tf(a.w);
            float4 w = *(const float4*)&W[(size_t)(n0 + row) * D_ + k0 + c4];
            Bs[row * PP + c4 + 0] = f2tf(w.x); Bs[row * PP + c4 + 1] = f2tf(w.y);
            Bs[row * PP + c4 + 2] = f2tf(w.z); Bs[row * PP + c4 + 3] = f2tf(w.w);
        }
        __syncthreads();

        #pragma unroll
        for (int ks = 0; ks < 2; ks++) {
            int kb = ks * 8;
            unsigned af[4][4], bf[4][2];
            #pragma unroll
            for (int mi = 0; mi < 4; mi++) {
                int rm = wm + mi * 16;
                af[mi][0] = As[(rm + g)     * PP + kb + tig];
                af[mi][1] = As[(rm + g + 8) * PP + kb + tig];
                af[mi][2] = As[(rm + g)     * PP + kb + tig + 4];
                af[mi][3] = As[(rm + g + 8) * PP + kb + tig + 4];
            }
            #pragma unroll
            for (int ni = 0; ni < 4; ni++) {
                int nb = wn + ni * 8;
                bf[ni][0] = Bs[(nb + g) * PP + kb + tig];
                bf[ni][1] = Bs[(nb + g) * PP + kb + tig + 4];
            }
            #pragma unroll
            for (int mi = 0; mi < 4; mi++)
                #pragma unroll
                for (int ni = 0; ni < 4; ni++)
                    mma8(acc[mi][ni], af[mi][0], af[mi][1], af[mi][2], af[mi][3],
                         bf[ni][0], bf[ni][1]);
        }
        __syncthreads();
    }

    // epilogue: bias + relu
    #pragma unroll
    for (int mi = 0; mi < 4; mi++) {
        int r0 = m0 + wm + mi * 16 + g;
        #pragma unroll
        for (int ni = 0; ni < 4; ni++) {
            int cc = n0 + wn + ni * 8 + 2 * tig;
            float bb0 = bias[cc], bb1 = bias[cc + 1];
            float2 v0, v1;
            v0.x = fmaxf(acc[mi][ni][0] + bb0, 0.0f);
            v0.y = fmaxf(acc[mi][ni][1] + bb1, 0.0f);
            v1.x = fmaxf(acc[mi][ni][2] + bb0, 0.0f);
            v1.y = fmaxf(acc[mi][ni][3] + bb1, 0.0f);
            *(float2*)&out[(size_t)r0 * D_ + cc]       = v0;
            *(float2*)&out[(size_t)(r0 + 8) * D_ + cc] = v1;
        }
    }
}

// ---------------- padding masks ----------------------------------------------
__global__ __launch_bounds__(256) void mask_kernel(
    const float* __restrict__ queries, const float* __restrict__ keys)
{
    __shared__ float rq[8];
    __shared__ float rk[8];
    const int row = blockIdx.x;
    const int tid = threadIdx.x;
    size_t base = (size_t)row * D_ + tid * 4;
    float4 q = *(const float4*)&queries[base];
    float4 k = *(const float4*)&keys[base];
    float sq = q.x + q.y + q.z + q.w;
    float sk = k.x + k.y + k.z + k.w;
    #pragma unroll
    for (int o = 16; o; o >>= 1) {
        sq += __shfl_xor_sync(0xffffffffu, sq, o);
        sk += __shfl_xor_sync(0xffffffffu, sk, o);
    }
    if ((tid & 31) == 0) { rq[tid >> 5] = sq; rk[tid >> 5] = sk; }
    __syncthreads();
    if (tid == 0) {
        float tq = 0.f, tk = 0.f;
        #pragma unroll
        for (int i = 0; i < 8; i++) { tq += rq[i]; tk += rk[i]; }
        g_qmask[row] = (tq != 0.0f) ? 1.0f : 0.0f;
        g_kmask[row] = (tk != 0.0f) ? 1.0f : 0.0f;
    }
}

// ---------------- causal flash attention (tf32 MMA, FA2 layout) --------------
// Block: 128 q-rows of one (b,h). 8 warps, warp w owns rows [w*16, w*16+16).
// Key tiles of 64. Softmax is warp-local (quad shuffles only).
#define QPP 68   // Q/P smem pitch
#define KPP 68   // K smem pitch
#define VPP 72   // V smem pitch
__global__ __launch_bounds__(256) void attn_kernel()
{
    extern __shared__ unsigned sm[];
    unsigned* qp  = sm;                        // 128 x QPP  (Q tile, then P)
    unsigned* Ksm = qp + 128 * QPP;            // 64 x KPP
    unsigned* Vsm = Ksm + 64 * KPP;            // 64 x VPP
    float*    kms = (float*)(Vsm + 64 * VPP);  // 64

    const int qb0  = blockIdx.x * 128;
    const int h    = blockIdx.y;
    const int b    = blockIdx.z;
    const int tid  = threadIdx.x;
    const int wid  = tid >> 5;
    const int lane = tid & 31;
    const int g    = lane >> 2;
    const int tig  = lane & 3;

    // load Q tile (cvt to tf32)
    #pragma unroll
    for (int lv = 0; lv < 8; lv++) {
        int idx = tid + lv * 256;              // 0..2047 float4 slots
        int r  = idx >> 4;
        int d4 = (idx & 15) * 4;
        float4 q = *(const float4*)&g_Q[(size_t)(b * S_ + qb0 + r) * D_ + h * DH_ + d4];
        qp[r * QPP + d4 + 0] = f2tf(q.x); qp[r * QPP + d4 + 1] = f2tf(q.y);
        qp[r * QPP + d4 + 2] = f2tf(q.z); qp[r * QPP + d4 + 3] = f2tf(q.w);
    }
    __syncthreads();

    // Q fragments -> registers (warp-private rows)
    unsigned qa[8][4];
    {
        int rb = wid * 16;
        #pragma unroll
        for (int kk = 0; kk < 8; kk++) {
            int kc = kk * 8;
            qa[kk][0] = qp[(rb + g)     * QPP + kc + tig];
            qa[kk][1] = qp[(rb + g + 8) * QPP + kc + tig];
            qa[kk][2] = qp[(rb + g)     * QPP + kc + tig + 4];
            qa[kk][3] = qp[(rb + g + 8) * QPP + kc + tig + 4];
        }
    }

    float oacc[8][4];
    #pragma unroll
    for (int ni = 0; ni < 8; ni++)
        #pragma unroll
        for (int e = 0; e < 4; e++) oacc[ni][e] = 0.0f;
    float mrow0 = -1e30f, mrow1 = -1e30f, lrow0 = 0.0f, lrow1 = 0.0f;

    const int row0 = qb0 + wid * 16 + g;
    const int row1 = row0 + 8;
    const int rmax = qb0 + wid * 16 + 15;
    const int ntile = (qb0 >> 6) + 2;

    for (int kt = 0; kt < ntile; kt++) {
        const int s0 = kt * 64;
        __syncthreads();
        // load K and V tiles (cvt to tf32)
        #pragma unroll
        for (int lv = 0; lv < 4; lv++) {
            int idx = tid + lv * 256;          // 0..1023
            int r  = idx >> 4;
            int d4 = (idx & 15) * 4;
            size_t base = (size_t)(b * S_ + s0 + r) * D_ + h * DH_ + d4;
            float4 k = *(const float4*)&g_K[base];
            Ksm[r * KPP + d4 + 0] = f2tf(k.x); Ksm[r * KPP + d4 + 1] = f2tf(k.y);
            Ksm[r * KPP + d4 + 2] = f2tf(k.z); Ksm[r * KPP + d4 + 3] = f2tf(k.w);
            float4 v = *(const float4*)&g_V[base];
            Vsm[r * VPP + d4 + 0] = f2tf(v.x); Vsm[r * VPP + d4 + 1] = f2tf(v.y);
            Vsm[r * VPP + d4 + 2] = f2tf(v.z); Vsm[r * VPP + d4 + 3] = f2tf(v.w);
        }
        if (tid < 64) kms[tid] = g_kmask[b * S_ + s0 + tid];
        __syncthreads();

        if (s0 > rmax) continue;   // this warp's rows never see these keys

        // S = Q K^T  (16 x 64 per warp)
        float sc[8][4];
        #pragma unroll
        for (int ni = 0; ni < 8; ni++)
            #pragma unroll
            for (int e = 0; e < 4; e++) sc[ni][e] = 0.0f;

        #pragma unroll
        for (int kk = 0; kk < 8; kk++) {
            int kc = kk * 8;
            #pragma unroll
            for (int ni = 0; ni < 8; ni++) {
                unsigned b0 = Ksm[(ni * 8 + g) * KPP + kc + tig];
                unsigned b1 = Ksm[(ni * 8 + g) * KPP + kc + tig + 4];
                mma8(sc[ni], qa[kk][0], qa[kk][1], qa[kk][2], qa[kk][3], b0, b1);
            }
        }

        // scale + masks
        float vm0 = -1e30f, vm1 = -1e30f;
        #pragma unroll
        for (int ni = 0; ni < 8; ni++) {
            #pragma unroll
            for (int e = 0; e < 2; e++) {
                int cl = ni * 8 + 2 * tig + e;
                int sg = s0 + cl;
                bool km = (kms[cl] != 0.0f);
                float v0 = sc[ni][e] * 0.125f;
                float v1 = sc[ni][2 + e] * 0.125f;
                v0 = (sg > row0 || !km) ? NEGV : v0;
                v1 = (sg > row1 || !km) ? NEGV : v1;
                sc[ni][e] = v0; sc[ni][2 + e] = v1;
                vm0 = fmaxf(vm0, v0); vm1 = fmaxf(vm1, v1);
            }
        }
        vm0 = fmaxf(vm0, __shfl_xor_sync(0xffffffffu, vm0, 1));
        vm0 = fmaxf(vm0, __shfl_xor_sync(0xffffffffu, vm0, 2));
        vm1 = fmaxf(vm1, __shfl_xor_sync(0xffffffffu, vm1, 1));
        vm1 = fmaxf(vm1, __shfl_xor_sync(0xffffffffu, vm1, 2));

        float mn0 = fmaxf(mrow0, vm0), mn1 = fmaxf(mrow1, vm1);
        float al0 = __expf(mrow0 - mn0), al1 = __expf(mrow1 - mn1);

        float ps0 = 0.0f, ps1 = 0.0f;
        int rb = wid * 16;
        #pragma unroll
        for (int ni = 0; ni < 8; ni++) {
            #pragma unroll
            for (int e = 0; e < 2; e++) {
                int cl = ni * 8 + 2 * tig + e;
                float p0 = __expf(sc[ni][e] - mn0);
                float p1 = __expf(sc[ni][2 + e] - mn1);
                ps0 += p0; ps1 += p1;
                qp[(rb + g)     * QPP + cl] = f2tf(p0);
                qp[(rb + g + 8) * QPP + cl] = f2tf(p1);
            }
        }
        ps0 += __shfl_xor_sync(0xffffffffu, ps0, 1);
        ps0 += __shfl_xor_sync(0xffffffffu, ps0, 2);
        ps1 += __shfl_xor_sync(0xffffffffu, ps1, 1);
        ps1 += __shfl_xor_sync(0xffffffffu, ps1, 2);

        lrow0 = lrow0 * al0 + ps0;
        lrow1 = lrow1 * al1 + ps1;
        mrow0 = mn0; mrow1 = mn1;
        #pragma unroll
        for (int ni = 0; ni < 8; ni++) {
            oacc[ni][0] *= al0; oacc[ni][1] *= al0;
            oacc[ni][2] *= al1; oacc[ni][3] *= al1;
        }
        __syncwarp();

        // O += P @ V   (k over 64 seq positions, n over 64 dh)
        #pragma unroll
        for (int kk = 0; kk < 8; kk++) {
            int kc = kk * 8;
            unsigned pa0 = qp[(rb + g)     * QPP + kc + tig];
            unsigned pa1 = qp[(rb + g + 8) * QPP + kc + tig];
            unsigned pa2 = qp[(rb + g)     * QPP + kc + tig + 4];
            unsigned pa3 = qp[(rb + g + 8) * QPP + kc + tig + 4];
            #pragma unroll
            for (int ni = 0; ni < 8; ni++) {
                unsigned b0 = Vsm[(kc + tig)     * VPP + ni * 8 + g];
                unsigned b1 = Vsm[(kc + tig + 4) * VPP + ni * 8 + g];
                mma8(oacc[ni], pa0, pa1, pa2, pa3, b0, b1);
            }
        }
    }

    // epilogue: normalize, query mask, store
    float qm0 = g_qmask[b * S_ + row0];
    float qm1 = g_qmask[b * S_ + row1];
    float inv0 = qm0 / lrow0;
    float inv1 = qm1 / lrow1;
    #pragma unroll
    for (int ni = 0; ni < 8; ni++) {
        int cc = h * DH_ + ni * 8 + 2 * tig;
        float2 v0, v1;
        v0.x = oacc[ni][0] * inv0; v0.y = oacc[ni][1] * inv0;
        v1.x = oacc[ni][2] * inv1; v1.y = oacc[ni][3] * inv1;
        *(float2*)&g_O[(size_t)(b * S_ + row0) * D_ + cc] = v0;
        *(float2*)&g_O[(size_t)(b * S_ + row1) * D_ + cc] = v1;
    }
}

// ---------------- residual + layernorm ---------------------------------------
__global__ __launch_bounds__(256) void ln_kernel(
    const float* __restrict__ qin, const float* __restrict__ gamma,
    const float* __restrict__ beta, float* __restrict__ out)
{
    __shared__ float red[8];
    __shared__ float red2[8];
    const int row = blockIdx.x;
    const int tid = threadIdx.x;
    size_t base = (size_t)row * D_ + tid * 4;

    float4 o = *(const float4*)&g_O[base];
    float4 q = *(const float4*)&qin[base];
    float x0 = o.x + q.x, x1 = o.y + q.y, x2 = o.z + q.z, x3 = o.w + q.w;

    float s = x0 + x1 + x2 + x3;
    #pragma unroll
    for (int off = 16; off; off >>= 1) s += __shfl_xor_sync(0xffffffffu, s, off);
    if ((tid & 31) == 0) red[tid >> 5] = s;
    __syncthreads();
    float tot = red[0] + red[1] + red[2] + red[3] + red[4] + red[5] + red[6] + red[7];
    float mean = tot * (1.0f / 1024.0f);

    float d0 = x0 - mean, d1 = x1 - mean, d2 = x2 - mean, d3 = x3 - mean;
    float sq = d0 * d0 + d1 * d1 + d2 * d2 + d3 * d3;
    #pragma unroll
    for (int off = 16; off; off >>= 1) sq += __shfl_xor_sync(0xffffffffu, sq, off);
    if ((tid & 31) == 0) red2[tid >> 5] = sq;
    __syncthreads();
    float ssq = red2[0] + red2[1] + red2[2] + red2[3] + red2[4] + red2[5] + red2[6] + red2[7];
    float stdv = sqrtf(ssq / 1023.0f);
    float inv = 1.0f / (stdv + 1e-8f);

    float4 gg = *(const float4*)&gamma[tid * 4];
    float4 be = *(const float4*)&beta[tid * 4];
    float4 y;
    y.x = gg.x * d0 * inv + be.x;
    y.y = gg.y * d1 * inv + be.y;
    y.z = gg.z * d2 * inv + be.z;
    y.w = gg.w * d3 * inv + be.w;
    *(float4*)&out[base] = y;
}

// ---------------- launch ------------------------------------------------------
extern "C" void kernel_launch(void* const* d_in, const int* in_sizes, int n_in,
                              void* d_out, int out_size)
{
    const float* queries = (const float*)d_in[0];
    const float* keys    = (const float*)d_in[1];
    const float* values  = (const float*)d_in[2];
    const float* Wq      = (const float*)d_in[3];
    const float* bq      = (const float*)d_in[4];
    const float* Wk      = (const float*)d_in[5];
    const float* bk      = (const float*)d_in[6];
    const float* Wv      = (const float*)d_in[7];
    const float* bv      = (const float*)d_in[8];
    const float* gamma   = (const float*)d_in[9];
    const float* beta    = (const float*)d_in[10];
    float* out = (float*)d_out;

    const int attn_smem = (128 * QPP + 64 * KPP + 64 * VPP) * 4 + 64 * 4;  // 70912 B
    cudaFuncSetAttribute(attn_kernel, cudaFuncAttributeMaxDynamicSharedMemorySize, attn_smem);

    proj_kernel<<<dim3(8, 32, 3), 256>>>(queries, keys, values, Wq, Wk, Wv, bq, bk, bv);
    mask_kernel<<<M_, 256>>>(queries, keys);
    attn_kernel<<<dim3(16, 16, 2), 256, attn_smem>>>();
    ln_kernel<<<M_, 256>>>(queries, gamma, beta, out);
}

// round 4
// speedup vs baseline: 3.7240x; 1.0936x over previous
#include <cuda_runtime.h>
#include <math.h>

#define B_  2
#define S_  2048
#define D_  1024
#define H_  16
#define DH_ 64
#define M_  (B_ * S_)
#define NEGV (-4294967295.0f)  // -2^32 + 1

// ---------------- scratch ----------------------------------------------------
__device__ float g_Q[M_ * D_];   // stored as tf32 bit patterns
__device__ float g_K[M_ * D_];
__device__ float g_V[M_ * D_];
__device__ float g_O[M_ * D_];
__device__ float g_kmask[M_];
__device__ float g_qmask[M_];

// ---------------- helpers -----------------------------------------------------
__device__ __forceinline__ unsigned f2tf(float f) {
    unsigned u;
    asm("cvt.rna.tf32.f32 %0, %1;" : "=r"(u) : "f"(f));
    return u;
}
__device__ __forceinline__ void mma8(float* c,
                                     unsigned a0, unsigned a1, unsigned a2, unsigned a3,
                                     unsigned b0, unsigned b1) {
    asm volatile(
        "mma.sync.aligned.m16n8k8.row.col.f32.tf32.tf32.f32 "
        "{%0,%1,%2,%3},{%4,%5,%6,%7},{%8,%9},{%0,%1,%2,%3};"
        : "+f"(c[0]), "+f"(c[1]), "+f"(c[2]), "+f"(c[3])
        : "r"(a0), "r"(a1), "r"(a2), "r"(a3), "r"(b0), "r"(b1));
}
__device__ __forceinline__ void cp16(void* smem, const void* gmem) {
    unsigned saddr = (unsigned)__cvta_generic_to_shared(smem);
    asm volatile("cp.async.cg.shared.global [%0], [%1], 16;" :: "r"(saddr), "l"(gmem));
}
#define CP_COMMIT() asm volatile("cp.async.commit_group;")
#define CP_WAIT(N)  asm volatile("cp.async.wait_group %0;" :: "n"(N))

// ---------------- fused QKV projection (tf32 MMA, 3-stage cp.async) ----------
// M=4096, N=1024, K=1024. BM=BN=128, BK=16, 256 threads, warp tile 64x32.
#define PP 20
#define NSTG 3
__global__ __launch_bounds__(256) void proj_kernel(
    const float* __restrict__ Xq, const float* __restrict__ Xk, const float* __restrict__ Xv,
    const float* __restrict__ Wq, const float* __restrict__ Wk, const float* __restrict__ Wv,
    const float* __restrict__ bq, const float* __restrict__ bk, const float* __restrict__ bv)
{
    extern __shared__ unsigned psm[];
    // layout: NSTG stages of [As(128*PP) | Bs(128*PP)]

    const float* X; const float* W; const float* bias; float* out;
    if (blockIdx.z == 0)      { X = Xq; W = Wq; bias = bq; out = g_Q; }
    else if (blockIdx.z == 1) { X = Xk; W = Wk; bias = bk; out = g_K; }
    else                      { X = Xv; W = Wv; bias = bv; out = g_V; }

    const int tid  = threadIdx.x;
    const int m0   = blockIdx.y * 128;
    const int n0   = blockIdx.x * 128;
    const int wid  = tid >> 5;
    const int lane = tid & 31;
    const int g    = lane >> 2;
    const int tig  = lane & 3;
    const int wm   = (wid >> 2) * 64;
    const int wn   = (wid & 3) * 32;

    float acc[4][4][4];
    #pragma unroll
    for (int i = 0; i < 4; i++)
        #pragma unroll
        for (int j = 0; j < 4; j++)
            #pragma unroll
            for (int e = 0; e < 4; e++) acc[i][j][e] = 0.0f;

    // prologue: issue first NSTG-1 stages
    #pragma unroll
    for (int s = 0; s < NSTG - 1; s++) {
        unsigned* As = psm + s * (2 * 128 * PP);
        unsigned* Bs = As + 128 * PP;
        int k0 = s * 16;
        #pragma unroll
        for (int lv = 0; lv < 2; lv++) {
            int idx = tid + lv * 256;
            int row = idx >> 2;
            int c4  = (idx & 3) * 4;
            cp16(&As[row * PP + c4], &X[(size_t)(m0 + row) * D_ + k0 + c4]);
            cp16(&Bs[row * PP + c4], &W[(size_t)(n0 + row) * D_ + k0 + c4]);
        }
        CP_COMMIT();
    }

    for (int it = 0; it < 64; it++) {
        CP_WAIT(NSTG - 2);
        __syncthreads();

        // prefetch stage it+NSTG-1
        if (it + NSTG - 1 < 64) {
            int s = (it + NSTG - 1) % NSTG;
            unsigned* As = psm + s * (2 * 128 * PP);
            unsigned* Bs = As + 128 * PP;
            int k0 = (it + NSTG - 1) * 16;
            #pragma unroll
            for (int lv = 0; lv < 2; lv++) {
                int idx = tid + lv * 256;
                int row = idx >> 2;
                int c4  = (idx & 3) * 4;
                cp16(&As[row * PP + c4], &X[(size_t)(m0 + row) * D_ + k0 + c4]);
                cp16(&Bs[row * PP + c4], &W[(size_t)(n0 + row) * D_ + k0 + c4]);
            }
        }
        CP_COMMIT();

        unsigned* As = psm + (it % NSTG) * (2 * 128 * PP);
        unsigned* Bs = As + 128 * PP;
        #pragma unroll
        for (int ks = 0; ks < 2; ks++) {
            int kb = ks * 8;
            unsigned af[4][4], bf[4][2];
            #pragma unroll
            for (int mi = 0; mi < 4; mi++) {
                int rm = wm + mi * 16;
                af[mi][0] = As[(rm + g)     * PP + kb + tig];
                af[mi][1] = As[(rm + g + 8) * PP + kb + tig];
                af[mi][2] = As[(rm + g)     * PP + kb + tig + 4];
                af[mi][3] = As[(rm + g + 8) * PP + kb + tig + 4];
            }
            #pragma unroll
            for (int ni = 0; ni < 4; ni++) {
                int nb = wn + ni * 8;
                bf[ni][0] = Bs[(nb + g) * PP + kb + tig];
                bf[ni][1] = Bs[(nb + g) * PP + kb + tig + 4];
            }
            #pragma unroll
            for (int mi = 0; mi < 4; mi++)
                #pragma unroll
                for (int ni = 0; ni < 4; ni++)
                    mma8(acc[mi][ni], af[mi][0], af[mi][1], af[mi][2], af[mi][3],
                         bf[ni][0], bf[ni][1]);
        }
    }

    // epilogue: bias + relu, stored pre-converted to tf32 bits
    #pragma unroll
    for (int mi = 0; mi < 4; mi++) {
        int r0 = m0 + wm + mi * 16 + g;
        #pragma unroll
        for (int ni = 0; ni < 4; ni++) {
            int cc = n0 + wn + ni * 8 + 2 * tig;
            float bb0 = bias[cc], bb1 = bias[cc + 1];
            float2 v0, v1;
            v0.x = __uint_as_float(f2tf(fmaxf(acc[mi][ni][0] + bb0, 0.0f)));
            v0.y = __uint_as_float(f2tf(fmaxf(acc[mi][ni][1] + bb1, 0.0f)));
            v1.x = __uint_as_float(f2tf(fmaxf(acc[mi][ni][2] + bb0, 0.0f)));
            v1.y = __uint_as_float(f2tf(fmaxf(acc[mi][ni][3] + bb1, 0.0f)));
            *(float2*)&out[(size_t)r0 * D_ + cc]       = v0;
            *(float2*)&out[(size_t)(r0 + 8) * D_ + cc] = v1;
        }
    }
}

// ---------------- padding masks ----------------------------------------------
__global__ __launch_bounds__(256) void mask_kernel(
    const float* __restrict__ queries, const float* __restrict__ keys)
{
    __shared__ float rq[8];
    __shared__ float rk[8];
    const int row = blockIdx.x;
    const int tid = threadIdx.x;
    size_t base = (size_t)row * D_ + tid * 4;
    float4 q = *(const float4*)&queries[base];
    float4 k = *(const float4*)&keys[base];
    float sq = q.x + q.y + q.z + q.w;
    float sk = k.x + k.y + k.z + k.w;
    #pragma unroll
    for (int o = 16; o; o >>= 1) {
        sq += __shfl_xor_sync(0xffffffffu, sq, o);
        sk += __shfl_xor_sync(0xffffffffu, sk, o);
    }
    if ((tid & 31) == 0) { rq[tid >> 5] = sq; rk[tid >> 5] = sk; }
    __syncthreads();
    if (tid == 0) {
        float tq = 0.f, tk = 0.f;
        #pragma unroll
        for (int i = 0; i < 8; i++) { tq += rq[i]; tk += rk[i]; }
        g_qmask[row] = (tq != 0.0f) ? 1.0f : 0.0f;
        g_kmask[row] = (tk != 0.0f) ? 1.0f : 0.0f;
    }
}

// ---------------- causal flash attention (tf32 MMA, double-buffered) ---------
#define QPP 68
#define KPP 68
#define VPP 72
__global__ __launch_bounds__(256) void attn_kernel()
{
    extern __shared__ unsigned sm[];
    unsigned* qp   = sm;                         // 128 x QPP (Q tile, then P)
    unsigned* Kst  = qp + 128 * QPP;             // 2 stages x 64 x KPP
    unsigned* Vst  = Kst + 2 * 64 * KPP;         // 2 stages x 64 x VPP
    float*    kms  = (float*)(Vst + 2 * 64 * VPP); // 2 stages x 64

    const int qt   = gridDim.x - 1 - blockIdx.x;   // heavy tiles first
    const int qb0  = qt * 128;
    const int h    = blockIdx.y;
    const int b    = blockIdx.z;
    const int tid  = threadIdx.x;
    const int wid  = tid >> 5;
    const int lane = tid & 31;
    const int g    = lane >> 2;
    const int tig  = lane & 3;

    const int ntile = (qb0 >> 6) + 2;

    // prologue: Q tile (group 0), then KV tile 0 (group 1)
    #pragma unroll
    for (int lv = 0; lv < 8; lv++) {
        int idx = tid + lv * 256;               // 0..2047 float4 slots
        int r  = idx >> 4;
        int d4 = (idx & 15) * 4;
        cp16(&qp[r * QPP + d4],
             &g_Q[(size_t)(b * S_ + qb0 + r) * D_ + h * DH_ + d4]);
    }
    CP_COMMIT();
    {
        unsigned* Ks = Kst;
        unsigned* Vs = Vst;
        #pragma unroll
        for (int lv = 0; lv < 4; lv++) {
            int idx = tid + lv * 256;
            int r  = idx >> 4;
            int d4 = (idx & 15) * 4;
            size_t base = (size_t)(b * S_ + r) * D_ + h * DH_ + d4;
            cp16(&Ks[r * KPP + d4], &g_K[base]);
            cp16(&Vs[r * VPP + d4], &g_V[base]);
        }
        if (tid < 16) cp16(&kms[tid * 4], &g_kmask[b * S_ + tid * 4]);
    }
    CP_COMMIT();

    CP_WAIT(1);          // Q ready
    __syncthreads();

    // Q fragments -> registers
    unsigned qa[8][4];
    {
        int rb = wid * 16;
        #pragma unroll
        for (int kk = 0; kk < 8; kk++) {
            int kc = kk * 8;
            qa[kk][0] = qp[(rb + g)     * QPP + kc + tig];
            qa[kk][1] = qp[(rb + g + 8) * QPP + kc + tig];
            qa[kk][2] = qp[(rb + g)     * QPP + kc + tig + 4];
            qa[kk][3] = qp[(rb + g + 8) * QPP + kc + tig + 4];
        }
    }

    float oacc[8][4];
    #pragma unroll
    for (int ni = 0; ni < 8; ni++)
        #pragma unroll
        for (int e = 0; e < 4; e++) oacc[ni][e] = 0.0f;
    float mrow0 = -1e30f, mrow1 = -1e30f, lrow0 = 0.0f, lrow1 = 0.0f;

    const int row0 = qb0 + wid * 16 + g;
    const int row1 = row0 + 8;
    const int rmax = qb0 + wid * 16 + 15;
    const int rb   = wid * 16;

    for (int kt = 0; kt < ntile; kt++) {
        const int cur = kt & 1;
        const int s0  = kt * 64;

        CP_WAIT(0);         // tile kt resident
        __syncthreads();

        // prefetch tile kt+1 into other stage
        if (kt + 1 < ntile) {
            const int nxt = cur ^ 1;
            const int sn  = (kt + 1) * 64;
            unsigned* Ks = Kst + nxt * 64 * KPP;
            unsigned* Vs = Vst + nxt * 64 * VPP;
            #pragma unroll
            for (int lv = 0; lv < 4; lv++) {
                int idx = tid + lv * 256;
                int r  = idx >> 4;
                int d4 = (idx & 15) * 4;
                size_t base = (size_t)(b * S_ + sn + r) * D_ + h * DH_ + d4;
                cp16(&Ks[r * KPP + d4], &g_K[base]);
                cp16(&Vs[r * VPP + d4], &g_V[base]);
            }
            if (tid < 16) cp16(&kms[nxt * 64 + tid * 4], &g_kmask[b * S_ + sn + tid * 4]);
        }
        CP_COMMIT();

        if (s0 > rmax) continue;          // warp's rows done with keys

        unsigned* Ksm = Kst + cur * 64 * KPP;
        unsigned* Vsm = Vst + cur * 64 * VPP;
        float*    kmc = kms + cur * 64;

        // S = Q K^T (16 x 64 per warp)
        float sc[8][4];
        #pragma unroll
        for (int ni = 0; ni < 8; ni++)
            #pragma unroll
            for (int e = 0; e < 4; e++) sc[ni][e] = 0.0f;

        #pragma unroll
        for (int kk = 0; kk < 8; kk++) {
            int kc = kk * 8;
            #pragma unroll
            for (int ni = 0; ni < 8; ni++) {
                unsigned b0 = Ksm[(ni * 8 + g) * KPP + kc + tig];
                unsigned b1 = Ksm[(ni * 8 + g) * KPP + kc + tig + 4];
                mma8(sc[ni], qa[kk][0], qa[kk][1], qa[kk][2], qa[kk][3], b0, b1);
            }
        }

        // scale + masks
        float vm0 = -1e30f, vm1 = -1e30f;
        #pragma unroll
        for (int ni = 0; ni < 8; ni++) {
            #pragma unroll
            for (int e = 0; e < 2; e++) {
                int cl = ni * 8 + 2 * tig + e;
                int sg = s0 + cl;
                bool km = (kmc[cl] != 0.0f);
                float v0 = sc[ni][e] * 0.125f;
                float v1 = sc[ni][2 + e] * 0.125f;
                v0 = (sg > row0 || !km) ? NEGV : v0;
                v1 = (sg > row1 || !km) ? NEGV : v1;
                sc[ni][e] = v0; sc[ni][2 + e] = v1;
                vm0 = fmaxf(vm0, v0); vm1 = fmaxf(vm1, v1);
            }
        }
        vm0 = fmaxf(vm0, __shfl_xor_sync(0xffffffffu, vm0, 1));
        vm0 = fmaxf(vm0, __shfl_xor_sync(0xffffffffu, vm0, 2));
        vm1 = fmaxf(vm1, __shfl_xor_sync(0xffffffffu, vm1, 1));
        vm1 = fmaxf(vm1, __shfl_xor_sync(0xffffffffu, vm1, 2));

        float mn0 = fmaxf(mrow0, vm0), mn1 = fmaxf(mrow1, vm1);
        float al0 = __expf(mrow0 - mn0), al1 = __expf(mrow1 - mn1);

        float ps0 = 0.0f, ps1 = 0.0f;
        #pragma unroll
        for (int ni = 0; ni < 8; ni++) {
            #pragma unroll
            for (int e = 0; e < 2; e++) {
                int cl = ni * 8 + 2 * tig + e;
                float p0 = __expf(sc[ni][e] - mn0);
                float p1 = __expf(sc[ni][2 + e] - mn1);
                ps0 += p0; ps1 += p1;
                qp[(rb + g)     * QPP + cl] = f2tf(p0);
                qp[(rb + g + 8) * QPP + cl] = f2tf(p1);
            }
        }
        ps0 += __shfl_xor_sync(0xffffffffu, ps0, 1);
        ps0 += __shfl_xor_sync(0xffffffffu, ps0, 2);
        ps1 += __shfl_xor_sync(0xffffffffu, ps1, 1);
        ps1 += __shfl_xor_sync(0xffffffffu, ps1, 2);

        lrow0 = lrow0 * al0 + ps0;
        lrow1 = lrow1 * al1 + ps1;
        mrow0 = mn0; mrow1 = mn1;
        #pragma unroll
        for (int ni = 0; ni < 8; ni++) {
            oacc[ni][0] *= al0; oacc[ni][1] *= al0;
            oacc[ni][2] *= al1; oacc[ni][3] *= al1;
        }
        __syncwarp();

        // O += P @ V
        #pragma unroll
        for (int kk = 0; kk < 8; kk++) {
            int kc = kk * 8;
            unsigned pa0 = qp[(rb + g)     * QPP + kc + tig];
            unsigned pa1 = qp[(rb + g + 8) * QPP + kc + tig];
            unsigned pa2 = qp[(rb + g)     * QPP + kc + tig + 4];
            unsigned pa3 = qp[(rb + g + 8) * QPP + kc + tig + 4];
            #pragma unroll
            for (int ni = 0; ni < 8; ni++) {
                unsigned b0 = Vsm[(kc + tig)     * VPP + ni * 8 + g];
                unsigned b1 = Vsm[(kc + tig + 4) * VPP + ni * 8 + g];
                mma8(oacc[ni], pa0, pa1, pa2, pa3, b0, b1);
            }
        }
    }

    // epilogue
    float qm0 = g_qmask[b * S_ + row0];
    float qm1 = g_qmask[b * S_ + row1];
    float inv0 = qm0 / lrow0;
    float inv1 = qm1 / lrow1;
    #pragma unroll
    for (int ni = 0; ni < 8; ni++) {
        int cc = h * DH_ + ni * 8 + 2 * tig;
        float2 v0, v1;
        v0.x = oacc[ni][0] * inv0; v0.y = oacc[ni][1] * inv0;
        v1.x = oacc[ni][2] * inv1; v1.y = oacc[ni][3] * inv1;
        *(float2*)&g_O[(size_t)(b * S_ + row0) * D_ + cc] = v0;
        *(float2*)&g_O[(size_t)(b * S_ + row1) * D_ + cc] = v1;
    }
}

// ---------------- residual + layernorm ---------------------------------------
__global__ __launch_bounds__(256) void ln_kernel(
    const float* __restrict__ qin, const float* __restrict__ gamma,
    const float* __restrict__ beta, float* __restrict__ out)
{
    __shared__ float red[8];
    __shared__ float red2[8];
    const int row = blockIdx.x;
    const int tid = threadIdx.x;
    size_t base = (size_t)row * D_ + tid * 4;

    float4 o = *(const float4*)&g_O[base];
    float4 q = *(const float4*)&qin[base];
    float x0 = o.x + q.x, x1 = o.y + q.y, x2 = o.z + q.z, x3 = o.w + q.w;

    float s = x0 + x1 + x2 + x3;
    #pragma unroll
    for (int off = 16; off; off >>= 1) s += __shfl_xor_sync(0xffffffffu, s, off);
    if ((tid & 31) == 0) red[tid >> 5] = s;
    __syncthreads();
    float tot = red[0] + red[1] + red[2] + red[3] + red[4] + red[5] + red[6] + red[7];
    float mean = tot * (1.0f / 1024.0f);

    float d0 = x0 - mean, d1 = x1 - mean, d2 = x2 - mean, d3 = x3 - mean;
    float sq = d0 * d0 + d1 * d1 + d2 * d2 + d3 * d3;
    #pragma unroll
    for (int off = 16; off; off >>= 1) sq += __shfl_xor_sync(0xffffffffu, sq, off);
    if ((tid & 31) == 0) red2[tid >> 5] = sq;
    __syncthreads();
    float ssq = red2[0] + red2[1] + red2[2] + red2[3] + red2[4] + red2[5] + red2[6] + red2[7];
    float stdv = sqrtf(ssq / 1023.0f);
    float inv = 1.0f / (stdv + 1e-8f);

    float4 gg = *(const float4*)&gamma[tid * 4];
    float4 be = *(const float4*)&beta[tid * 4];
    float4 y;
    y.x = gg.x * d0 * inv + be.x;
    y.y = gg.y * d1 * inv + be.y;
    y.z = gg.z * d2 * inv + be.z;
    y.w = gg.w * d3 * inv + be.w;
    *(float4*)&out[base] = y;
}

// ---------------- launch ------------------------------------------------------
extern "C" void kernel_launch(void* const* d_in, const int* in_sizes, int n_in,
                              void* d_out, int out_size)
{
    const float* queries = (const float*)d_in[0];
    const float* keys    = (const float*)d_in[1];
    const float* values  = (const float*)d_in[2];
    const float* Wq      = (const float*)d_in[3];
    const float* bq      = (const float*)d_in[4];
    const float* Wk      = (const float*)d_in[5];
    const float* bk      = (const float*)d_in[6];
    const float* Wv      = (const float*)d_in[7];
    const float* bv      = (const float*)d_in[8];
    const float* gamma   = (const float*)d_in[9];
    const float* beta    = (const float*)d_in[10];
    float* out = (float*)d_out;

    const int proj_smem = NSTG * 2 * 128 * PP * sizeof(unsigned);            // 61440 B
    const int attn_smem = (128 * QPP + 2 * 64 * KPP + 2 * 64 * VPP + 128) * 4; // 107008 B
    cudaFuncSetAttribute(proj_kernel, cudaFuncAttributeMaxDynamicSharedMemorySize, proj_smem);
    cudaFuncSetAttribute(attn_kernel, cudaFuncAttributeMaxDynamicSharedMemorySize, attn_smem);

    proj_kernel<<<dim3(8, 32, 3), 256, proj_smem>>>(queries, keys, values, Wq, Wk, Wv, bq, bk, bv);
    mask_kernel<<<M_, 256>>>(queries, keys);
    attn_kernel<<<dim3(16, 16, 2), 256, attn_smem>>>();
    ln_kernel<<<M_, 256>>>(queries, gamma, beta, out);
}

// round 5
// speedup vs baseline: 6.7832x; 1.8215x over previous
#include <cuda_runtime.h>
#include <cuda_bf16.h>
#include <math.h>

#define B_  2
#define S_  2048
#define D_  1024
#define H_  16
#define DH_ 64
#define M_  (B_ * S_)
#define NEGV (-4294967295.0f)  // -2^32 + 1

// ---------------- scratch ----------------------------------------------------
__device__ __nv_bfloat16 g_xq[M_ * D_];   // bf16 copies of inputs
__device__ __nv_bfloat16 g_xk[M_ * D_];
__device__ __nv_bfloat16 g_xv[M_ * D_];
__device__ __nv_bfloat16 g_wq[D_ * D_];
__device__ __nv_bfloat16 g_wk[D_ * D_];
__device__ __nv_bfloat16 g_wv[D_ * D_];
__device__ __nv_bfloat16 g_Q[M_ * D_];    // proj outputs (bf16)
__device__ __nv_bfloat16 g_K[M_ * D_];
__device__ __nv_bfloat16 g_V[M_ * D_];
__device__ __nv_bfloat16 g_Vt[B_ * H_ * DH_ * S_];  // V transposed per (b,h)
__device__ float g_O[M_ * D_];
__device__ float g_kmask[M_];
__device__ float g_qmask[M_];

// ---------------- helpers ------------------------------------------------------
__device__ __forceinline__ unsigned pk2(float lo, float hi) {
    unsigned r;
    asm("cvt.rn.bf16x2.f32 %0, %1, %2;" : "=r"(r) : "f"(hi), "f"(lo));
    return r;
}
__device__ __forceinline__ void mmabf(float* c,
                                      unsigned a0, unsigned a1, unsigned a2, unsigned a3,
                                      unsigned b0, unsigned b1) {
    asm volatile(
        "mma.sync.aligned.m16n8k16.row.col.f32.bf16.bf16.f32 "
        "{%0,%1,%2,%3},{%4,%5,%6,%7},{%8,%9},{%0,%1,%2,%3};"
        : "+f"(c[0]), "+f"(c[1]), "+f"(c[2]), "+f"(c[3])
        : "r"(a0), "r"(a1), "r"(a2), "r"(a3), "r"(b0), "r"(b1));
}
__device__ __forceinline__ void cp16(void* smem, const void* gmem) {
    unsigned saddr = (unsigned)__cvta_generic_to_shared(smem);
    asm volatile("cp.async.cg.shared.global [%0], [%1], 16;" :: "r"(saddr), "l"(gmem));
}
#define CP_COMMIT() asm volatile("cp.async.commit_group;")
#define CP_WAIT(N)  asm volatile("cp.async.wait_group %0;" :: "n"(N))

// swizzles: rows of 64B (4 chunks) and 128B (8 chunks)
__device__ __forceinline__ int sw4(int row, int c) { return c ^ ((row >> 1) & 3); }
__device__ __forceinline__ int sw8(int row, int c) { return c ^ (row & 7); }
__device__ __forceinline__ unsigned ld32(const char* p) { return *(const unsigned*)p; }

// ---------------- fp32 -> bf16 conversion pre-pass -----------------------------
__global__ __launch_bounds__(256) void cvt_kernel(
    const float* __restrict__ q, const float* __restrict__ k, const float* __restrict__ v,
    const float* __restrict__ wq, const float* __restrict__ wk, const float* __restrict__ wv)
{
    const int z = blockIdx.y;
    const float* src; __nv_bfloat16* dst; int n;
    if (z == 0)      { src = q;  dst = g_xq; n = M_ * D_; }
    else if (z == 1) { src = k;  dst = g_xk; n = M_ * D_; }
    else if (z == 2) { src = v;  dst = g_xv; n = M_ * D_; }
    else if (z == 3) { src = wq; dst = g_wq; n = D_ * D_; }
    else if (z == 4) { src = wk; dst = g_wk; n = D_ * D_; }
    else             { src = wv; dst = g_wv; n = D_ * D_; }

    int base = (blockIdx.x * 256 + threadIdx.x) * 8;
    if (base >= n) return;
    float4 a = *(const float4*)&src[base];
    float4 b = *(const float4*)&src[base + 4];
    uint4 o;
    o.x = pk2(a.x, a.y); o.y = pk2(a.z, a.w);
    o.z = pk2(b.x, b.y); o.w = pk2(b.z, b.w);
    *(uint4*)&dst[base] = o;
}

// ---------------- fused QKV projection (bf16 MMA, 3-stage cp.async) -----------
// M=4096, N=1024, K=1024. BM=BN=128, BK=32, 256 threads, warp tile 64x32.
#define NSTG 3
#define PSTG (2 * 128 * 64)   // bytes per stage (A 8KB + B 8KB)
__global__ __launch_bounds__(256) void proj_kernel(int unused)
{
    extern __shared__ char psm[];

    const __nv_bfloat16* X; const __nv_bfloat16* W; __nv_bfloat16* out;
    if (blockIdx.z == 0)      { X = g_xq; W = g_wq; out = g_Q; }
    else if (blockIdx.z == 1) { X = g_xk; W = g_wk; out = g_K; }
    else                      { X = g_xv; W = g_wv; out = g_V; }

    const int tid  = threadIdx.x;
    const int m0   = blockIdx.y * 128;
    const int n0   = blockIdx.x * 128;
    const int wid  = tid >> 5;
    const int lane = tid & 31;
    const int g    = lane >> 2;
    const int tig  = lane & 3;
    const int wm   = (wid >> 2) * 64;
    const int wn   = (wid & 3) * 32;

    float acc[4][4][4];
    #pragma unroll
    for (int i = 0; i < 4; i++)
        #pragma unroll
        for (int j = 0; j < 4; j++)
            #pragma unroll
            for (int e = 0; e < 4; e++) acc[i][j][e] = 0.0f;

    // stage loader: 128 rows x 4 chunks (16B) for A and B each
    auto load_stage = [&](int stage, int k0) {
        char* As = psm + stage * PSTG;
        char* Bs = As + 128 * 64;
        #pragma unroll
        for (int lv = 0; lv < 2; lv++) {
            int idx = tid + lv * 256;     // 0..511
            int row = idx >> 2;
            int c   = idx & 3;
            int cs  = sw4(row, c);
            cp16(As + row * 64 + cs * 16, &X[(size_t)(m0 + row) * D_ + k0 + c * 8]);
            cp16(Bs + row * 64 + cs * 16, &W[(size_t)(n0 + row) * D_ + k0 + c * 8]);
        }
    };

    #pragma unroll
    for (int s = 0; s < NSTG - 1; s++) { load_stage(s, s * 32); CP_COMMIT(); }

    for (int it = 0; it < 32; it++) {
        CP_WAIT(NSTG - 2);
        __syncthreads();

        if (it + NSTG - 1 < 32) load_stage((it + NSTG - 1) % NSTG, (it + NSTG - 1) * 32);
        CP_COMMIT();

        char* As = psm + (it % NSTG) * PSTG;
        char* Bs = As + 128 * 64;
        #pragma unroll
        for (int ks = 0; ks < 2; ks++) {
            unsigned af[4][4], bf[4][2];
            #pragma unroll
            for (int mi = 0; mi < 4; mi++) {
                int r0 = wm + mi * 16 + g;
                int r1 = r0 + 8;
                af[mi][0] = ld32(As + r0 * 64 + sw4(r0, 2 * ks) * 16 + tig * 4);
                af[mi][1] = ld32(As + r1 * 64 + sw4(r1, 2 * ks) * 16 + tig * 4);
                af[mi][2] = ld32(As + r0 * 64 + sw4(r0, 2 * ks + 1) * 16 + tig * 4);
                af[mi][3] = ld32(As + r1 * 64 + sw4(r1, 2 * ks + 1) * 16 + tig * 4);
            }
            #pragma unroll
            for (int ni = 0; ni < 4; ni++) {
                int rn = wn + ni * 8 + g;
                bf[ni][0] = ld32(Bs + rn * 64 + sw4(rn, 2 * ks) * 16 + tig * 4);
                bf[ni][1] = ld32(Bs + rn * 64 + sw4(rn, 2 * ks + 1) * 16 + tig * 4);
            }
            #pragma unroll
            for (int mi = 0; mi < 4; mi++)
                #pragma unroll
                for (int ni = 0; ni < 4; ni++)
                    mmabf(acc[mi][ni], af[mi][0], af[mi][1], af[mi][2], af[mi][3],
                          bf[ni][0], bf[ni][1]);
        }
    }

    // epilogue: relu (bias is zero in this problem but harness may vary: biases
    // are inputs; apply them) -> bf16 pairs
    // NOTE: biases passed via globals? they are inputs; fetch from const mem args.
    #pragma unroll
    for (int mi = 0; mi < 4; mi++) {
        int r0 = m0 + wm + mi * 16 + g;
        #pragma unroll
        for (int ni = 0; ni < 4; ni++) {
            int cc = n0 + wn + ni * 8 + 2 * tig;
            *(unsigned*)&out[(size_t)r0 * D_ + cc] =
                pk2(fmaxf(acc[mi][ni][0], 0.0f), fmaxf(acc[mi][ni][1], 0.0f));
            *(unsigned*)&out[(size_t)(r0 + 8) * D_ + cc] =
                pk2(fmaxf(acc[mi][ni][2], 0.0f), fmaxf(acc[mi][ni][3], 0.0f));
        }
    }
}

// bias add variant kept general: separate tiny kernel applies bias before relu is
// impossible post-relu; instead proj assumes zero bias. To stay correct for
// arbitrary bias, we add bias inside proj via global pointers:
__device__ const float* g_bias_q;
__device__ const float* g_bias_k;
__device__ const float* g_bias_v;

__global__ __launch_bounds__(256) void proj_kernel_bias(
    const float* __restrict__ bq, const float* __restrict__ bk, const float* __restrict__ bv)
{
    extern __shared__ char psm[];

    const __nv_bfloat16* X; const __nv_bfloat16* W; __nv_bfloat16* out;
    const float* bias;
    if (blockIdx.z == 0)      { X = g_xq; W = g_wq; out = g_Q; bias = bq; }
    else if (blockIdx.z == 1) { X = g_xk; W = g_wk; out = g_K; bias = bk; }
    else                      { X = g_xv; W = g_wv; out = g_V; bias = bv; }

    const int tid  = threadIdx.x;
    const int m0   = blockIdx.y * 128;
    const int n0   = blockIdx.x * 128;
    const int wid  = tid >> 5;
    const int lane = tid & 31;
    const int g    = lane >> 2;
    const int tig  = lane & 3;
    const int wm   = (wid >> 2) * 64;
    const int wn   = (wid & 3) * 32;

    float acc[4][4][4];
    #pragma unroll
    for (int i = 0; i < 4; i++)
        #pragma unroll
        for (int j = 0; j < 4; j++)
            #pragma unroll
            for (int e = 0; e < 4; e++) acc[i][j][e] = 0.0f;

    auto load_stage = [&](int stage, int k0) {
        char* As = psm + stage * PSTG;
        char* Bs = As + 128 * 64;
        #pragma unroll
        for (int lv = 0; lv < 2; lv++) {
            int idx = tid + lv * 256;
            int row = idx >> 2;
            int c   = idx & 3;
            int cs  = sw4(row, c);
            cp16(As + row * 64 + cs * 16, &X[(size_t)(m0 + row) * D_ + k0 + c * 8]);
            cp16(Bs + row * 64 + cs * 16, &W[(size_t)(n0 + row) * D_ + k0 + c * 8]);
        }
    };

    #pragma unroll
    for (int s = 0; s < NSTG - 1; s++) { load_stage(s, s * 32); CP_COMMIT(); }

    for (int it = 0; it < 32; it++) {
        CP_WAIT(NSTG - 2);
        __syncthreads();
        if (it + NSTG - 1 < 32) load_stage((it + NSTG - 1) % NSTG, (it + NSTG - 1) * 32);
        CP_COMMIT();

        char* As = psm + (it % NSTG) * PSTG;
        char* Bs = As + 128 * 64;
        #pragma unroll
        for (int ks = 0; ks < 2; ks++) {
            unsigned af[4][4], bf[4][2];
            #pragma unroll
            for (int mi = 0; mi < 4; mi++) {
                int r0 = wm + mi * 16 + g;
                int r1 = r0 + 8;
                af[mi][0] = ld32(As + r0 * 64 + sw4(r0, 2 * ks) * 16 + tig * 4);
                af[mi][1] = ld32(As + r1 * 64 + sw4(r1, 2 * ks) * 16 + tig * 4);
                af[mi][2] = ld32(As + r0 * 64 + sw4(r0, 2 * ks + 1) * 16 + tig * 4);
                af[mi][3] = ld32(As + r1 * 64 + sw4(r1, 2 * ks + 1) * 16 + tig * 4);
            }
            #pragma unroll
            for (int ni = 0; ni < 4; ni++) {
                int rn = wn + ni * 8 + g;
                bf[ni][0] = ld32(Bs + rn * 64 + sw4(rn, 2 * ks) * 16 + tig * 4);
                bf[ni][1] = ld32(Bs + rn * 64 + sw4(rn, 2 * ks + 1) * 16 + tig * 4);
            }
            #pragma unroll
            for (int mi = 0; mi < 4; mi++)
                #pragma unroll
                for (int ni = 0; ni < 4; ni++)
                    mmabf(acc[mi][ni], af[mi][0], af[mi][1], af[mi][2], af[mi][3],
                          bf[ni][0], bf[ni][1]);
        }
    }

    #pragma unroll
    for (int mi = 0; mi < 4; mi++) {
        int r0 = m0 + wm + mi * 16 + g;
        #pragma unroll
        for (int ni = 0; ni < 4; ni++) {
            int cc = n0 + wn + ni * 8 + 2 * tig;
            float bb0 = bias[cc], bb1 = bias[cc + 1];
            *(unsigned*)&out[(size_t)r0 * D_ + cc] =
                pk2(fmaxf(acc[mi][ni][0] + bb0, 0.0f), fmaxf(acc[mi][ni][1] + bb1, 0.0f));
            *(unsigned*)&out[(size_t)(r0 + 8) * D_ + cc] =
                pk2(fmaxf(acc[mi][ni][2] + bb0, 0.0f), fmaxf(acc[mi][ni][3] + bb1, 0.0f));
        }
    }
}

// ---------------- V transpose: g_V [s][h*64+d] -> g_Vt [(b,h)][d][s] ----------
__global__ __launch_bounds__(256) void vt_kernel()
{
    __shared__ __nv_bfloat16 tsm[64 * 72];
    const int s0 = blockIdx.x * 64;
    const int bh = blockIdx.y;             // b*16 + h
    const int b  = bh >> 4;
    const int h  = bh & 15;
    const int tid = threadIdx.x;

    #pragma unroll
    for (int lv = 0; lv < 2; lv++) {
        int idx = tid + lv * 256;          // 64 rows x 8 chunks
        int r = idx >> 3;
        int c = idx & 7;
        *(uint4*)&tsm[r * 72 + c * 8] =
            *(const uint4*)&g_V[(size_t)(b * S_ + s0 + r) * D_ + h * DH_ + c * 8];
    }
    __syncthreads();

    #pragma unroll
    for (int i = 0; i < 2; i++) {
        int d = (tid & 63);
        int c = (tid >> 6) + i * 4;        // 0..7
        uint4 o;
        unsigned* po = (unsigned*)&o;
        #pragma unroll
        for (int jj = 0; jj < 4; jj++) {
            unsigned short lo = *(unsigned short*)&tsm[(c * 8 + jj * 2)     * 72 + d];
            unsigned short hi = *(unsigned short*)&tsm[(c * 8 + jj * 2 + 1) * 72 + d];
            po[jj] = (unsigned)lo | ((unsigned)hi << 16);
        }
        *(uint4*)&g_Vt[(size_t)bh * DH_ * S_ + (size_t)d * S_ + s0 + c * 8] = o;
    }
}

// ---------------- padding masks -------------------------------------------------
__global__ __launch_bounds__(256) void mask_kernel(
    const float* __restrict__ queries, const float* __restrict__ keys)
{
    __shared__ float rq[8];
    __shared__ float rk[8];
    const int row = blockIdx.x;
    const int tid = threadIdx.x;
    size_t base = (size_t)row * D_ + tid * 4;
    float4 q = *(const float4*)&queries[base];
    float4 k = *(const float4*)&keys[base];
    float sq = q.x + q.y + q.z + q.w;
    float sk = k.x + k.y + k.z + k.w;
    #pragma unroll
    for (int o = 16; o; o >>= 1) {
        sq += __shfl_xor_sync(0xffffffffu, sq, o);
        sk += __shfl_xor_sync(0xffffffffu, sk, o);
    }
    if ((tid & 31) == 0) { rq[tid >> 5] = sq; rk[tid >> 5] = sk; }
    __syncthreads();
    if (tid == 0) {
        float tq = 0.f, tk = 0.f;
        #pragma unroll
        for (int i = 0; i < 8; i++) { tq += rq[i]; tk += rk[i]; }
        g_qmask[row] = (tq != 0.0f) ? 1.0f : 0.0f;
        g_kmask[row] = (tk != 0.0f) ? 1.0f : 0.0f;
    }
}

// ---------------- causal flash attention (bf16 MMA, double-buffered) -----------
// smem: Q/P 128x128B, K 2x64x128B, Vt 2x64x128B, kmask 2x64 f32  = 49.7 KB
#define AQ_OFF  0
#define AK_OFF  (128 * 128)
#define AV_OFF  (AK_OFF + 2 * 64 * 128)
#define AM_OFF  (AV_OFF + 2 * 64 * 128)
#define ATTN_SMEM (AM_OFF + 2 * 64 * 4)
__global__ __launch_bounds__(256) void attn_kernel()
{
    extern __shared__ char sm[];
    char*  qp  = sm + AQ_OFF;
    char*  Kst = sm + AK_OFF;
    char*  Vst = sm + AV_OFF;
    float* kms = (float*)(sm + AM_OFF);

    const int qt   = gridDim.x - 1 - blockIdx.x;
    const int qb0  = qt * 128;
    const int h    = blockIdx.y;
    const int b    = blockIdx.z;
    const int tid  = threadIdx.x;
    const int wid  = tid >> 5;
    const int lane = tid & 31;
    const int g    = lane >> 2;
    const int tig  = lane & 3;
    const int rb   = wid * 16;

    const int ntile = (qb0 >> 6) + 2;
    const __nv_bfloat16* Vtg = g_Vt + (size_t)(b * H_ + h) * DH_ * S_;

    // prologue: Q tile (group 0)
    #pragma unroll
    for (int lv = 0; lv < 4; lv++) {
        int idx = tid + lv * 256;          // 128 rows x 8 chunks
        int r = idx >> 3;
        int c = idx & 7;
        cp16(qp + r * 128 + sw8(r, c) * 16,
             &g_Q[(size_t)(b * S_ + qb0 + r) * D_ + h * DH_ + c * 8]);
    }
    CP_COMMIT();
    // KV tile 0 (group 1)
    {
        #pragma unroll
        for (int lv = 0; lv < 2; lv++) {
            int idx = tid + lv * 256;      // 64 rows x 8 chunks
            int r = idx >> 3;
            int c = idx & 7;
            cp16(Kst + r * 128 + sw8(r, c) * 16,
                 &g_K[(size_t)(b * S_ + r) * D_ + h * DH_ + c * 8]);
            cp16(Vst + r * 128 + sw8(r, c) * 16, &Vtg[(size_t)r * S_ + c * 8]);
        }
        if (tid < 16) cp16(&kms[tid * 4], &g_kmask[b * S_ + tid * 4]);
    }
    CP_COMMIT();

    CP_WAIT(1);
    __syncthreads();

    // Q fragments -> registers (4 ksteps of k16)
    unsigned qa[4][4];
    {
        int r0 = rb + g, r1 = rb + g + 8;
        #pragma unroll
        for (int ks = 0; ks < 4; ks++) {
            qa[ks][0] = ld32(qp + r0 * 128 + sw8(r0, 2 * ks) * 16 + tig * 4);
            qa[ks][1] = ld32(qp + r1 * 128 + sw8(r1, 2 * ks) * 16 + tig * 4);
            qa[ks][2] = ld32(qp + r0 * 128 + sw8(r0, 2 * ks + 1) * 16 + tig * 4);
            qa[ks][3] = ld32(qp + r1 * 128 + sw8(r1, 2 * ks + 1) * 16 + tig * 4);
        }
    }

    float oacc[8][4];
    #pragma unroll
    for (int ni = 0; ni < 8; ni++)
        #pragma unroll
        for (int e = 0; e < 4; e++) oacc[ni][e] = 0.0f;
    float mrow0 = -1e30f, mrow1 = -1e30f, lrow0 = 0.0f, lrow1 = 0.0f;

    const int row0 = qb0 + rb + g;
    const int row1 = row0 + 8;
    const int rmax = qb0 + rb + 15;

    for (int kt = 0; kt < ntile; kt++) {
        const int cur = kt & 1;
        const int s0  = kt * 64;

        CP_WAIT(0);
        __syncthreads();

        if (kt + 1 < ntile) {
            const int nxt = cur ^ 1;
            const int sn  = (kt + 1) * 64;
            char* Ks = Kst + nxt * 64 * 128;
            char* Vs = Vst + nxt * 64 * 128;
            #pragma unroll
            for (int lv = 0; lv < 2; lv++) {
                int idx = tid + lv * 256;
                int r = idx >> 3;
                int c = idx & 7;
                cp16(Ks + r * 128 + sw8(r, c) * 16,
                     &g_K[(size_t)(b * S_ + sn + r) * D_ + h * DH_ + c * 8]);
                cp16(Vs + r * 128 + sw8(r, c) * 16, &Vtg[(size_t)r * S_ + sn + c * 8]);
            }
            if (tid < 16) cp16(&kms[nxt * 64 + tid * 4], &g_kmask[b * S_ + sn + tid * 4]);
        }
        CP_COMMIT();

        if (s0 > rmax) continue;

        char*  Ksm = Kst + cur * 64 * 128;
        char*  Vsm = Vst + cur * 64 * 128;
        float* kmc = kms + cur * 64;

        // S = Q K^T (16 x 64 per warp)
        float sc[8][4];
        #pragma unroll
        for (int ni = 0; ni < 8; ni++)
            #pragma unroll
            for (int e = 0; e < 4; e++) sc[ni][e] = 0.0f;

        #pragma unroll
        for (int ks = 0; ks < 4; ks++) {
            #pragma unroll
            for (int ni = 0; ni < 8; ni++) {
                int rn = ni * 8 + g;
                unsigned b0 = ld32(Ksm + rn * 128 + sw8(rn, 2 * ks) * 16 + tig * 4);
                unsigned b1 = ld32(Ksm + rn * 128 + sw8(rn, 2 * ks + 1) * 16 + tig * 4);
                mmabf(sc[ni], qa[ks][0], qa[ks][1], qa[ks][2], qa[ks][3], b0, b1);
            }
        }

        // scale + masks
        float vm0 = -1e30f, vm1 = -1e30f;
        #pragma unroll
        for (int ni = 0; ni < 8; ni++) {
            #pragma unroll
            for (int e = 0; e < 2; e++) {
                int cl = ni * 8 + 2 * tig + e;
                int sg = s0 + cl;
                bool km = (kmc[cl] != 0.0f);
                float v0 = sc[ni][e] * 0.125f;
                float v1 = sc[ni][2 + e] * 0.125f;
                v0 = (sg > row0 || !km) ? NEGV : v0;
                v1 = (sg > row1 || !km) ? NEGV : v1;
                sc[ni][e] = v0; sc[ni][2 + e] = v1;
                vm0 = fmaxf(vm0, v0); vm1 = fmaxf(vm1, v1);
            }
        }
        vm0 = fmaxf(vm0, __shfl_xor_sync(0xffffffffu, vm0, 1));
        vm0 = fmaxf(vm0, __shfl_xor_sync(0xffffffffu, vm0, 2));
        vm1 = fmaxf(vm1, __shfl_xor_sync(0xffffffffu, vm1, 1));
        vm1 = fmaxf(vm1, __shfl_xor_sync(0xffffffffu, vm1, 2));

        float mn0 = fmaxf(mrow0, vm0), mn1 = fmaxf(mrow1, vm1);
        float al0 = __expf(mrow0 - mn0), al1 = __expf(mrow1 - mn1);

        float ps0 = 0.0f, ps1 = 0.0f;
        {
            int r0 = rb + g, r1 = rb + g + 8;
            #pragma unroll
            for (int ni = 0; ni < 8; ni++) {
                float p00 = __expf(sc[ni][0] - mn0);
                float p01 = __expf(sc[ni][1] - mn0);
                float p10 = __expf(sc[ni][2] - mn1);
                float p11 = __expf(sc[ni][3] - mn1);
                ps0 += p00 + p01; ps1 += p10 + p11;
                *(unsigned*)(qp + r0 * 128 + sw8(r0, ni) * 16 + tig * 4) = pk2(p00, p01);
                *(unsigned*)(qp + r1 * 128 + sw8(r1, ni) * 16 + tig * 4) = pk2(p10, p11);
            }
        }
        ps0 += __shfl_xor_sync(0xffffffffu, ps0, 1);
        ps0 += __shfl_xor_sync(0xffffffffu, ps0, 2);
        ps1 += __shfl_xor_sync(0xffffffffu, ps1, 1);
        ps1 += __shfl_xor_sync(0xffffffffu, ps1, 2);

        lrow0 = lrow0 * al0 + ps0;
        lrow1 = lrow1 * al1 + ps1;
        mrow0 = mn0; mrow1 = mn1;
        #pragma unroll
        for (int ni = 0; ni < 8; ni++) {
            oacc[ni][0] *= al0; oacc[ni][1] *= al0;
            oacc[ni][2] *= al1; oacc[ni][3] *= al1;
        }
        __syncwarp();

        // O += P @ V  (k = 64 seq -> 4 ksteps)
        {
            int r0 = rb + g, r1 = rb + g + 8;
            #pragma unroll
            for (int ks = 0; ks < 4; ks++) {
                unsigned pa0 = ld32(qp + r0 * 128 + sw8(r0, 2 * ks) * 16 + tig * 4);
                unsigned pa1 = ld32(qp + r1 * 128 + sw8(r1, 2 * ks) * 16 + tig * 4);
                unsigned pa2 = ld32(qp + r0 * 128 + sw8(r0, 2 * ks + 1) * 16 + tig * 4);
                unsigned pa3 = ld32(qp + r1 * 128 + sw8(r1, 2 * ks + 1) * 16 + tig * 4);
                #pragma unroll
                for (int ni = 0; ni < 8; ni++) {
                    int rn = ni * 8 + g;
                    unsigned b0 = ld32(Vsm + rn * 128 + sw8(rn, 2 * ks) * 16 + tig * 4);
                    unsigned b1 = ld32(Vsm + rn * 128 + sw8(rn, 2 * ks + 1) * 16 + tig * 4);
                    mmabf(oacc[ni], pa0, pa1, pa2, pa3, b0, b1);
                }
            }
        }
    }

    // epilogue
    float qm0 = g_qmask[b * S_ + row0];
    float qm1 = g_qmask[b * S_ + row1];
    float inv0 = qm0 / lrow0;
    float inv1 = qm1 / lrow1;
    #pragma unroll
    for (int ni = 0; ni < 8; ni++) {
        int cc = h * DH_ + ni * 8 + 2 * tig;
        float2 v0, v1;
        v0.x = oacc[ni][0] * inv0; v0.y = oacc[ni][1] * inv0;
        v1.x = oacc[ni][2] * inv1; v1.y = oacc[ni][3] * inv1;
        *(float2*)&g_O[(size_t)(b * S_ + row0) * D_ + cc] = v0;
        *(float2*)&g_O[(size_t)(b * S_ + row1) * D_ + cc] = v1;
    }
}

// ---------------- residual + layernorm ------------------------------------------
__global__ __launch_bounds__(256) void ln_kernel(
    const float* __restrict__ qin, const float* __restrict__ gamma,
    const float* __restrict__ beta, float* __restrict__ out)
{
    __shared__ float red[8];
    __shared__ float red2[8];
    const int row = blockIdx.x;
    const int tid = threadIdx.x;
    size_t base = (size_t)row * D_ + tid * 4;

    float4 o = *(const float4*)&g_O[base];
    float4 q = *(const float4*)&qin[base];
    float x0 = o.x + q.x, x1 = o.y + q.y, x2 = o.z + q.z, x3 = o.w + q.w;

    float s = x0 + x1 + x2 + x3;
    #pragma unroll
    for (int off = 16; off; off >>= 1) s += __shfl_xor_sync(0xffffffffu, s, off);
    if ((tid & 31) == 0) red[tid >> 5] = s;
    __syncthreads();
    float tot = red[0] + red[1] + red[2] + red[3] + red[4] + red[5] + red[6] + red[7];
    float mean = tot * (1.0f / 1024.0f);

    float d0 = x0 - mean, d1 = x1 - mean, d2 = x2 - mean, d3 = x3 - mean;
    float sq = d0 * d0 + d1 * d1 + d2 * d2 + d3 * d3;
    #pragma unroll
    for (int off = 16; off; off >>= 1) sq += __shfl_xor_sync(0xffffffffu, sq, off);
    if ((tid & 31) == 0) red2[tid >> 5] = sq;
    __syncthreads();
    float ssq = red2[0] + red2[1] + red2[2] + red2[3] + red2[4] + red2[5] + red2[6] + red2[7];
    float stdv = sqrtf(ssq / 1023.0f);
    float inv = 1.0f / (stdv + 1e-8f);

    float4 gg = *(const float4*)&gamma[tid * 4];
    float4 be = *(const float4*)&beta[tid * 4];
    float4 y;
    y.x = gg.x * d0 * inv + be.x;
    y.y = gg.y * d1 * inv + be.y;
    y.z = gg.z * d2 * inv + be.z;
    y.w = gg.w * d3 * inv + be.w;
    *(float4*)&out[base] = y;
}

// ---------------- launch ----------------------------------------------------------
extern "C" void kernel_launch(void* const* d_in, const int* in_sizes, int n_in,
                              void* d_out, int out_size)
{
    const float* queries = (const float*)d_in[0];
    const float* keys    = (const float*)d_in[1];
    const float* values  = (const float*)d_in[2];
    const float* Wq      = (const float*)d_in[3];
    const float* bq      = (const float*)d_in[4];
    const float* Wk      = (const float*)d_in[5];
    const float* bk      = (const float*)d_in[6];
    const float* Wv      = (const float*)d_in[7];
    const float* bv      = (const float*)d_in[8];
    const float* gamma   = (const float*)d_in[9];
    const float* beta    = (const float*)d_in[10];
    float* out = (float*)d_out;

    const int proj_smem = NSTG * PSTG;       // 49152 B
    cudaFuncSetAttribute(proj_kernel_bias, cudaFuncAttributeMaxDynamicSharedMemorySize, proj_smem);
    cudaFuncSetAttribute(attn_kernel, cudaFuncAttributeMaxDynamicSharedMemorySize, ATTN_SMEM);

    cvt_kernel<<<dim3(2048, 6), 256>>>(queries, keys, values, Wq, Wk, Wv);
    mask_kernel<<<M_, 256>>>(queries, keys);
    proj_kernel_bias<<<dim3(8, 32, 3), 256, proj_smem>>>(bq, bk, bv);
    vt_kernel<<<dim3(32, 32), 256>>>();
    attn_kernel<<<dim3(16, 16, 2), 256, ATTN_SMEM>>>();
    ln_kernel<<<M_, 256>>>(queries, gamma, beta, out);
}

// round 7
// speedup vs baseline: 7.7197x; 1.1381x over previous
#include <cuda_runtime.h>
#include <cuda_bf16.h>
#include <math.h>
#include <cstdint>

#define B_  2
#define S_  2048
#define D_  1024
#define H_  16
#define DH_ 64
#define M_  (B_ * S_)
#define NEGV (-4294967295.0f)  // -2^32 + 1

// ---------------- scratch ----------------------------------------------------
__device__ __nv_bfloat16 g_xq[M_ * D_];
__device__ __nv_bfloat16 g_xk[M_ * D_];
__device__ __nv_bfloat16 g_xv[M_ * D_];
__device__ __nv_bfloat16 g_wq[D_ * D_];
__device__ __nv_bfloat16 g_wk[D_ * D_];
__device__ __nv_bfloat16 g_wv[D_ * D_];
__device__ __nv_bfloat16 g_Q[M_ * D_];
__device__ __nv_bfloat16 g_K[M_ * D_];
__device__ __nv_bfloat16 g_V[M_ * D_];
__device__ __nv_bfloat16 g_Vt[B_ * H_ * DH_ * S_];
__device__ float g_O[M_ * D_];
__device__ float g_kmask[M_];
__device__ float g_qmask[M_];

// ---------------- helpers ------------------------------------------------------
__device__ __forceinline__ unsigned pk2(float lo, float hi) {
    unsigned r;
    asm("cvt.rn.bf16x2.f32 %0, %1, %2;" : "=r"(r) : "f"(hi), "f"(lo));
    return r;
}
__device__ __forceinline__ void mmabf(float* c,
                                      unsigned a0, unsigned a1, unsigned a2, unsigned a3,
                                      unsigned b0, unsigned b1) {
    asm volatile(
        "mma.sync.aligned.m16n8k16.row.col.f32.bf16.bf16.f32 "
        "{%0,%1,%2,%3},{%4,%5,%6,%7},{%8,%9},{%0,%1,%2,%3};"
        : "+f"(c[0]), "+f"(c[1]), "+f"(c[2]), "+f"(c[3])
        : "r"(a0), "r"(a1), "r"(a2), "r"(a3), "r"(b0), "r"(b1));
}
__device__ __forceinline__ void cp16(void* smem, const void* gmem) {
    unsigned saddr = (unsigned)__cvta_generic_to_shared(smem);
    asm volatile("cp.async.cg.shared.global [%0], [%1], 16;" :: "r"(saddr), "l"(gmem));
}
#define CP_COMMIT() asm volatile("cp.async.commit_group;")
#define CP_WAIT(N)  asm volatile("cp.async.wait_group %0;" :: "n"(N))
__device__ __forceinline__ int sw4(int row, int c) { return c ^ ((row >> 1) & 3); }
__device__ __forceinline__ int sw8(int row, int c) { return c ^ (row & 7); }
__device__ __forceinline__ void ldm_x4(unsigned* r, const char* p) {
    uint32_t a = (uint32_t)__cvta_generic_to_shared(p);
    asm volatile("ldmatrix.sync.aligned.m8n8.x4.shared.b16 {%0,%1,%2,%3}, [%4];"
        : "=r"(r[0]), "=r"(r[1]), "=r"(r[2]), "=r"(r[3]) : "r"(a));
}

// ---------------- fp32 -> bf16 conversion + row masks ---------------------------
// For z==0/1 each block covers exactly 2 rows -> compute q/k padding masks inline.
__global__ __launch_bounds__(256) void cvt_kernel(
    const float* __restrict__ q, const float* __restrict__ k, const float* __restrict__ v,
    const float* __restrict__ wq, const float* __restrict__ wk, const float* __restrict__ wv)
{
    __shared__ float rs[8];
    const int z = blockIdx.y;
    const float* src; __nv_bfloat16* dst; int n;
    if (z == 0)      { src = q;  dst = g_xq; n = M_ * D_; }
    else if (z == 1) { src = k;  dst = g_xk; n = M_ * D_; }
    else if (z == 2) { src = v;  dst = g_xv; n = M_ * D_; }
    else if (z == 3) { src = wq; dst = g_wq; n = D_ * D_; }
    else if (z == 4) { src = wk; dst = g_wk; n = D_ * D_; }
    else             { src = wv; dst = g_wv; n = D_ * D_; }

    const int tid = threadIdx.x;
    int base = (blockIdx.x * 256 + tid) * 8;
    if (base >= n) return;
    float4 a = *(const float4*)&src[base];
    float4 b = *(const float4*)&src[base + 4];
    uint4 o;
    o.x = pk2(a.x, a.y); o.y = pk2(a.z, a.w);
    o.z = pk2(b.x, b.y); o.w = pk2(b.z, b.w);
    *(uint4*)&dst[base] = o;

    if (z < 2) {
        float s = a.x + a.y + a.z + a.w + b.x + b.y + b.z + b.w;
        #pragma unroll
        for (int off = 16; off; off >>= 1) s += __shfl_xor_sync(0xffffffffu, s, off);
        if ((tid & 31) == 0) rs[tid >> 5] = s;
        __syncthreads();
        float* msk = (z == 0) ? g_qmask : g_kmask;
        if (tid == 0) {
            float t = rs[0] + rs[1] + rs[2] + rs[3];
            msk[blockIdx.x * 2] = (t != 0.0f) ? 1.0f : 0.0f;
        } else if (tid == 128) {
            float t = rs[4] + rs[5] + rs[6] + rs[7];
            msk[blockIdx.x * 2 + 1] = (t != 0.0f) ? 1.0f : 0.0f;
        }
    }
}

// ---------------- fused QKV projection (bf16 MMA + ldmatrix, 3-stage cp.async) --
// M=4096, N=1024, K=1024. BM=BN=128, BK=32, 256 threads, warp tile 64x32.
#define NSTG 3
#define PSTG (2 * 128 * 64)
__global__ __launch_bounds__(256) void proj_kernel(
    const float* __restrict__ bq, const float* __restrict__ bk, const float* __restrict__ bv)
{
    extern __shared__ char psm[];

    const __nv_bfloat16* X; const __nv_bfloat16* W; __nv_bfloat16* out; const float* bias;
    if (blockIdx.z == 0)      { X = g_xq; W = g_wq; out = g_Q; bias = bq; }
    else if (blockIdx.z == 1) { X = g_xk; W = g_wk; out = g_K; bias = bk; }
    else                      { X = g_xv; W = g_wv; out = g_V; bias = bv; }

    const int tid  = threadIdx.x;
    const int m0   = blockIdx.y * 128;
    const int n0   = blockIdx.x * 128;
    const int wid  = tid >> 5;
    const int lane = tid & 31;
    const int g    = lane >> 2;
    const int tig  = lane & 3;
    const int wm   = (wid >> 2) * 64;
    const int wn   = (wid & 3) * 32;
    const int sub  = lane >> 3;          // ldmatrix sub-matrix id
    const int rin  = lane & 7;

    // ldmatrix lane-row/chunk offsets
    const int a_row = (sub & 1) * 8 + rin;   // + wm + mi*16
    const int a_co  = sub >> 1;              // + 2*ks
    const int b_row = (sub >> 1) * 8 + rin;  // + wn + p*16
    const int b_co  = sub & 1;               // + 2*ks

    float acc[4][4][4];
    #pragma unroll
    for (int i = 0; i < 4; i++)
        #pragma unroll
        for (int j = 0; j < 4; j++)
            #pragma unroll
            for (int e = 0; e < 4; e++) acc[i][j][e] = 0.0f;

    auto load_stage = [&](int stage, int k0) {
        char* As = psm + stage * PSTG;
        char* Bs = As + 128 * 64;
        #pragma unroll
        for (int lv = 0; lv < 2; lv++) {
            int idx = tid + lv * 256;
            int row = idx >> 2;
            int c   = idx & 3;
            int cs  = sw4(row, c);
            cp16(As + row * 64 + cs * 16, &X[(size_t)(m0 + row) * D_ + k0 + c * 8]);
            cp16(Bs + row * 64 + cs * 16, &W[(size_t)(n0 + row) * D_ + k0 + c * 8]);
        }
    };

    #pragma unroll
    for (int s = 0; s < NSTG - 1; s++) { load_stage(s, s * 32); CP_COMMIT(); }

    for (int it = 0; it < 32; it++) {
        CP_WAIT(NSTG - 2);
        __syncthreads();
        if (it + NSTG - 1 < 32) load_stage((it + NSTG - 1) % NSTG, (it + NSTG - 1) * 32);
        CP_COMMIT();

        char* As = psm + (it % NSTG) * PSTG;
        char* Bs = As + 128 * 64;
        #pragma unroll
        for (int ks = 0; ks < 2; ks++) {
            unsigned af[4][4], bf[2][4];
            #pragma unroll
            for (int mi = 0; mi < 4; mi++) {
                int r = wm + mi * 16 + a_row;
                ldm_x4(af[mi], As + r * 64 + sw4(r, 2 * ks + a_co) * 16);
            }
            #pragma unroll
            for (int p = 0; p < 2; p++) {
                int r = wn + p * 16 + b_row;
                ldm_x4(bf[p], Bs + r * 64 + sw4(r, 2 * ks + b_co) * 16);
            }
            #pragma unroll
            for (int mi = 0; mi < 4; mi++)
                #pragma unroll
                for (int ni = 0; ni < 4; ni++)
                    mmabf(acc[mi][ni], af[mi][0], af[mi][1], af[mi][2], af[mi][3],
                          bf[ni >> 1][(ni & 1) * 2], bf[ni >> 1][(ni & 1) * 2 + 1]);
        }
    }

    #pragma unroll
    for (int mi = 0; mi < 4; mi++) {
        int r0 = m0 + wm + mi * 16 + g;
        #pragma unroll
        for (int ni = 0; ni < 4; ni++) {
            int cc = n0 + wn + ni * 8 + 2 * tig;
            float bb0 = bias[cc], bb1 = bias[cc + 1];
            *(unsigned*)&out[(size_t)r0 * D_ + cc] =
                pk2(fmaxf(acc[mi][ni][0] + bb0, 0.0f), fmaxf(acc[mi][ni][1] + bb1, 0.0f));
            *(unsigned*)&out[(size_t)(r0 + 8) * D_ + cc] =
                pk2(fmaxf(acc[mi][ni][2] + bb0, 0.0f), fmaxf(acc[mi][ni][3] + bb1, 0.0f));
        }
    }
}

// ---------------- V transpose ------------------------------------------------------
__global__ __launch_bounds__(256) void vt_kernel()
{
    __shared__ __nv_bfloat16 tsm[64 * 72];
    const int s0 = blockIdx.x * 64;
    const int bh = blockIdx.y;
    const int b  = bh >> 4;
    const int h  = bh & 15;
    const int tid = threadIdx.x;

    #pragma unroll
    for (int lv = 0; lv < 2; lv++) {
        int idx = tid + lv * 256;
        int r = idx >> 3;
        int c = idx & 7;
        *(uint4*)&tsm[r * 72 + c * 8] =
            *(const uint4*)&g_V[(size_t)(b * S_ + s0 + r) * D_ + h * DH_ + c * 8];
    }
    __syncthreads();

    #pragma unroll
    for (int i = 0; i < 2; i++) {
        int d = (tid & 63);
        int c = (tid >> 6) + i * 4;
        uint4 o;
        unsigned* po = (unsigned*)&o;
        #pragma unroll
        for (int jj = 0; jj < 4; jj++) {
            unsigned short lo = *(unsigned short*)&tsm[(c * 8 + jj * 2)     * 72 + d];
            unsigned short hi = *(unsigned short*)&tsm[(c * 8 + jj * 2 + 1) * 72 + d];
            po[jj] = (unsigned)lo | ((unsigned)hi << 16);
        }
        *(uint4*)&g_Vt[(size_t)bh * DH_ * S_ + (size_t)d * S_ + s0 + c * 8] = o;
    }
}

// ---------------- causal flash attention (bf16 MMA + ldmatrix, P in regs) ----------
#define AQ_OFF  0
#define AK_OFF  (128 * 128)
#define AV_OFF  (AK_OFF + 2 * 64 * 128)
#define AM_OFF  (AV_OFF + 2 * 64 * 128)
#define ATTN_SMEM (AM_OFF + 2 * 64 * 4)
__global__ __launch_bounds__(256) void attn_kernel()
{
    extern __shared__ char sm[];
    char*  qp  = sm + AQ_OFF;
    char*  Kst = sm + AK_OFF;
    char*  Vst = sm + AV_OFF;
    float* kms = (float*)(sm + AM_OFF);

    const int qt   = gridDim.x - 1 - blockIdx.x;
    const int qb0  = qt * 128;
    const int h    = blockIdx.y;
    const int b    = blockIdx.z;
    const int tid  = threadIdx.x;
    const int wid  = tid >> 5;
    const int lane = tid & 31;
    const int g    = lane >> 2;
    const int tig  = lane & 3;
    const int rb   = wid * 16;
    const int sub  = lane >> 3;
    const int rin  = lane & 7;

    const int a_row = (sub & 1) * 8 + rin;   // A-operand ldmatrix row offset
    const int a_co  = sub >> 1;
    const int b_row = (sub >> 1) * 8 + rin;  // B-operand ldmatrix row offset
    const int b_co  = sub & 1;

    const int ntile = (qb0 >> 6) + 2;
    const __nv_bfloat16* Vtg = g_Vt + (size_t)(b * H_ + h) * DH_ * S_;

    #pragma unroll
    for (int lv = 0; lv < 4; lv++) {
        int idx = tid + lv * 256;
        int r = idx >> 3;
        int c = idx & 7;
        cp16(qp + r * 128 + sw8(r, c) * 16,
             &g_Q[(size_t)(b * S_ + qb0 + r) * D_ + h * DH_ + c * 8]);
    }
    CP_COMMIT();
    {
        #pragma unroll
        for (int lv = 0; lv < 2; lv++) {
            int idx = tid + lv * 256;
            int r = idx >> 3;
            int c = idx & 7;
            cp16(Kst + r * 128 + sw8(r, c) * 16,
                 &g_K[(size_t)(b * S_ + r) * D_ + h * DH_ + c * 8]);
            cp16(Vst + r * 128 + sw8(r, c) * 16, &Vtg[(size_t)r * S_ + c * 8]);
        }
        if (tid < 16) cp16(&kms[tid * 4], &g_kmask[b * S_ + tid * 4]);
    }
    CP_COMMIT();

    CP_WAIT(1);
    __syncthreads();

    // Q fragments via ldmatrix (4 ksteps of k16)
    unsigned qa[4][4];
    #pragma unroll
    for (int ks = 0; ks < 4; ks++) {
        int r = rb + a_row;
        ldm_x4(qa[ks], qp + r * 128 + sw8(r, 2 * ks + a_co) * 16);
    }

    float oacc[8][4];
    #pragma unroll
    for (int ni = 0; ni < 8; ni++)
        #pragma unroll
        for (int e = 0; e < 4; e++) oacc[ni][e] = 0.0f;
    float mrow0 = -1e30f, mrow1 = -1e30f, lrow0 = 0.0f, lrow1 = 0.0f;

    const int row0 = qb0 + rb + g;
    const int row1 = row0 + 8;
    const int rmax = qb0 + rb + 15;

    for (int kt = 0; kt < ntile; kt++) {
        const int cur = kt & 1;
        const int s0  = kt * 64;

        CP_WAIT(0);
        __syncthreads();

        if (kt + 1 < ntile) {
            const int nxt = cur ^ 1;
            const int sn  = (kt + 1) * 64;
            char* Ks = Kst + nxt * 64 * 128;
            char* Vs = Vst + nxt * 64 * 128;
            #pragma unroll
            for (int lv = 0; lv < 2; lv++) {
                int idx = tid + lv * 256;
                int r = idx >> 3;
                int c = idx & 7;
                cp16(Ks + r * 128 + sw8(r, c) * 16,
                     &g_K[(size_t)(b * S_ + sn + r) * D_ + h * DH_ + c * 8]);
                cp16(Vs + r * 128 + sw8(r, c) * 16, &Vtg[(size_t)r * S_ + sn + c * 8]);
            }
            if (tid < 16) cp16(&kms[nxt * 64 + tid * 4], &g_kmask[b * S_ + sn + tid * 4]);
        }
        CP_COMMIT();

        if (s0 > rmax) continue;

        char*  Ksm = Kst + cur * 64 * 128;
        char*  Vsm = Vst + cur * 64 * 128;
        float* kmc = kms + cur * 64;

        // S = Q K^T (16 x 64 per warp), K fragments via ldmatrix
        float sc[8][4];
        #pragma unroll
        for (int ni = 0; ni < 8; ni++)
            #pragma unroll
            for (int e = 0; e < 4; e++) sc[ni][e] = 0.0f;

        #pragma unroll
        for (int ks = 0; ks < 4; ks++) {
            #pragma unroll
            for (int p = 0; p < 4; p++) {
                unsigned kf[4];
                int r = p * 16 + b_row;
                ldm_x4(kf, Ksm + r * 128 + sw8(r, 2 * ks + b_co) * 16);
                mmabf(sc[2 * p],     qa[ks][0], qa[ks][1], qa[ks][2], qa[ks][3], kf[0], kf[1]);
                mmabf(sc[2 * p + 1], qa[ks][0], qa[ks][1], qa[ks][2], qa[ks][3], kf[2], kf[3]);
            }
        }

        // scale + masks
        float vm0 = -1e30f, vm1 = -1e30f;
        #pragma unroll
        for (int ni = 0; ni < 8; ni++) {
            #pragma unroll
            for (int e = 0; e < 2; e++) {
                int cl = ni * 8 + 2 * tig + e;
                int sg = s0 + cl;
                bool km = (kmc[cl] != 0.0f);
                float v0 = sc[ni][e] * 0.125f;
                float v1 = sc[ni][2 + e] * 0.125f;
                v0 = (sg > row0 || !km) ? NEGV : v0;
                v1 = (sg > row1 || !km) ? NEGV : v1;
                sc[ni][e] = v0; sc[ni][2 + e] = v1;
                vm0 = fmaxf(vm0, v0); vm1 = fmaxf(vm1, v1);
            }
        }
        vm0 = fmaxf(vm0, __shfl_xor_sync(0xffffffffu, vm0, 1));
        vm0 = fmaxf(vm0, __shfl_xor_sync(0xffffffffu, vm0, 2));
        vm1 = fmaxf(vm1, __shfl_xor_sync(0xffffffffu, vm1, 1));
        vm1 = fmaxf(vm1, __shfl_xor_sync(0xffffffffu, vm1, 2));

        float mn0 = fmaxf(mrow0, vm0), mn1 = fmaxf(mrow1, vm1);
        float al0 = __expf(mrow0 - mn0), al1 = __expf(mrow1 - mn1);

        // P in registers: pack accumulator fragment directly into A-operand layout
        unsigned pp[8][2];
        float ps0 = 0.0f, ps1 = 0.0f;
        #pragma unroll
        for (int ni = 0; ni < 8; ni++) {
            float p00 = __expf(sc[ni][0] - mn0);
            float p01 = __expf(sc[ni][1] - mn0);
            float p10 = __expf(sc[ni][2] - mn1);
            float p11 = __expf(sc[ni][3] - mn1);
            ps0 += p00 + p01; ps1 += p10 + p11;
            pp[ni][0] = pk2(p00, p01);
            pp[ni][1] = pk2(p10, p11);
        }
        ps0 += __shfl_xor_sync(0xffffffffu, ps0, 1);
        ps0 += __shfl_xor_sync(0xffffffffu, ps0, 2);
        ps1 += __shfl_xor_sync(0xffffffffu, ps1, 1);
        ps1 += __shfl_xor_sync(0xffffffffu, ps1, 2);

        lrow0 = lrow0 * al0 + ps0;
        lrow1 = lrow1 * al1 + ps1;
        mrow0 = mn0; mrow1 = mn1;
        #pragma unroll
        for (int ni = 0; ni < 8; ni++) {
            oacc[ni][0] *= al0; oacc[ni][1] *= al0;
            oacc[ni][2] *= al1; oacc[ni][3] *= al1;
        }

        // O += P @ V, V fragments via ldmatrix
        #pragma unroll
        for (int ks = 0; ks < 4; ks++) {
            unsigned pa0 = pp[2 * ks][0];
            unsigned pa1 = pp[2 * ks][1];
            unsigned pa2 = pp[2 * ks + 1][0];
            unsigned pa3 = pp[2 * ks + 1][1];
            #pragma unroll
            for (int p = 0; p < 4; p++) {
                unsigned vf[4];
                int r = p * 16 + b_row;
                ldm_x4(vf, Vsm + r * 128 + sw8(r, 2 * ks + b_co) * 16);
                mmabf(oacc[2 * p],     pa0, pa1, pa2, pa3, vf[0], vf[1]);
                mmabf(oacc[2 * p + 1], pa0, pa1, pa2, pa3, vf[2], vf[3]);
            }
        }
    }

    float qm0 = g_qmask[b * S_ + row0];
    float qm1 = g_qmask[b * S_ + row1];
    float inv0 = qm0 / lrow0;
    float inv1 = qm1 / lrow1;
    #pragma unroll
    for (int ni = 0; ni < 8; ni++) {
        int cc = h * DH_ + ni * 8 + 2 * tig;
        float2 v0, v1;
        v0.x = oacc[ni][0] * inv0; v0.y = oacc[ni][1] * inv0;
        v1.x = oacc[ni][2] * inv1; v1.y = oacc[ni][3] * inv1;
        *(float2*)&g_O[(size_t)(b * S_ + row0) * D_ + cc] = v0;
        *(float2*)&g_O[(size_t)(b * S_ + row1) * D_ + cc] = v1;
    }
}

// ---------------- residual + layernorm ------------------------------------------
__global__ __launch_bounds__(256) void ln_kernel(
    const float* __restrict__ qin, const float* __restrict__ gamma,
    const float* __restrict__ beta, float* __restrict__ out)
{
    __shared__ float red[8];
    __shared__ float red2[8];
    const int row = blockIdx.x;
    const int tid = threadIdx.x;
    size_t base = (size_t)row * D_ + tid * 4;

    float4 o = *(const float4*)&g_O[base];
    float4 q = *(const float4*)&qin[base];
    float x0 = o.x + q.x, x1 = o.y + q.y, x2 = o.z + q.z, x3 = o.w + q.w;

    float s = x0 + x1 + x2 + x3;
    #pragma unroll
    for (int off = 16; off; off >>= 1) s += __shfl_xor_sync(0xffffffffu, s, off);
    if ((tid & 31) == 0) red[tid >> 5] = s;
    __syncthreads();
    float tot = red[0] + red[1] + red[2] + red[3] + red[4] + red[5] + red[6] + red[7];
    float mean = tot * (1.0f / 1024.0f);

    float d0 = x0 - mean, d1 = x1 - mean, d2 = x2 - mean, d3 = x3 - mean;
    float sq = d0 * d0 + d1 * d1 + d2 * d2 + d3 * d3;
    #pragma unroll
    for (int off = 16; off; off >>= 1) sq += __shfl_xor_sync(0xffffffffu, sq, off);
    if ((tid & 31) == 0) red2[tid >> 5] = sq;
    __syncthreads();
    float ssq = red2[0] + red2[1] + red2[2] + red2[3] + red2[4] + red2[5] + red2[6] + red2[7];
    float stdv = sqrtf(ssq / 1023.0f);
    float inv = 1.0f / (stdv + 1e-8f);

    float4 gg = *(const float4*)&gamma[tid * 4];
    float4 be = *(const float4*)&beta[tid * 4];
    float4 y;
    y.x = gg.x * d0 * inv + be.x;
    y.y = gg.y * d1 * inv + be.y;
    y.z = gg.z * d2 * inv + be.z;
    y.w = gg.w * d3 * inv + be.w;
    *(float4*)&out[base] = y;
}

// ---------------- launch -----------------------------------------------------------
extern "C" void kernel_launch(void* const* d_in, const int* in_sizes, int n_in,
                              void* d_out, int out_size)
{
    const float* queries = (const float*)d_in[0];
    const float* keys    = (const float*)d_in[1];
    const float* values  = (const float*)d_in[2];
    const float* Wq      = (const float*)d_in[3];
    const float* bq      = (const float*)d_in[4];
    const float* Wk      = (const float*)d_in[5];
    const float* bk      = (const float*)d_in[6];
    const float* Wv      = (const float*)d_in[7];
    const float* bv      = (const float*)d_in[8];
    const float* gamma   = (const float*)d_in[9];
    const float* beta    = (const float*)d_in[10];
    float* out = (float*)d_out;

    const int proj_smem = NSTG * PSTG;   // 49152 B
    cudaFuncSetAttribute(proj_kernel, cudaFuncAttributeMaxDynamicSharedMemorySize, proj_smem);
    cudaFuncSetAttribute(attn_kernel, cudaFuncAttributeMaxDynamicSharedMemorySize, ATTN_SMEM);

    cvt_kernel<<<dim3(2048, 6), 256>>>(queries, keys, values, Wq, Wk, Wv);
    proj_kernel<<<dim3(8, 32, 3), 256, proj_smem>>>(bq, bk, bv);
    vt_kernel<<<dim3(32, 32), 256>>>();
    attn_kernel<<<dim3(16, 16, 2), 256, ATTN_SMEM>>>();
    ln_kernel<<<M_, 256>>>(queries, gamma, beta, out);
}

// round 8
// speedup vs baseline: 8.4318x; 1.0923x over previous
#include <cuda_runtime.h>
#include <cuda_bf16.h>
#include <math.h>
#include <cstdint>

#define B_  2
#define S_  2048
#define D_  1024
#define H_  16
#define DH_ 64
#define M_  (B_ * S_)
#define NEGV (-4294967295.0f)  // -2^32 + 1

// ---------------- scratch ----------------------------------------------------
__device__ __nv_bfloat16 g_xq[M_ * D_];
__device__ __nv_bfloat16 g_xk[M_ * D_];
__device__ __nv_bfloat16 g_xv[M_ * D_];
__device__ __nv_bfloat16 g_wq[D_ * D_];
__device__ __nv_bfloat16 g_wk[D_ * D_];
__device__ __nv_bfloat16 g_wv[D_ * D_];
__device__ __nv_bfloat16 g_Q[M_ * D_];
__device__ __nv_bfloat16 g_K[M_ * D_];
__device__ __nv_bfloat16 g_V[M_ * D_];
__device__ __nv_bfloat16 g_Vt[B_ * H_ * DH_ * S_];
__device__ float g_O[M_ * D_];
__device__ float g_kmask[M_];
__device__ float g_qmask[M_];

// ---------------- helpers ------------------------------------------------------
__device__ __forceinline__ unsigned pk2(float lo, float hi) {
    unsigned r;
    asm("cvt.rn.bf16x2.f32 %0, %1, %2;" : "=r"(r) : "f"(hi), "f"(lo));
    return r;
}
__device__ __forceinline__ float ex2(float x) {
    float y;
    asm("ex2.approx.f32 %0, %1;" : "=f"(y) : "f"(x));
    return y;
}
__device__ __forceinline__ void mmabf(float* c,
                                      unsigned a0, unsigned a1, unsigned a2, unsigned a3,
                                      unsigned b0, unsigned b1) {
    asm volatile(
        "mma.sync.aligned.m16n8k16.row.col.f32.bf16.bf16.f32 "
        "{%0,%1,%2,%3},{%4,%5,%6,%7},{%8,%9},{%0,%1,%2,%3};"
        : "+f"(c[0]), "+f"(c[1]), "+f"(c[2]), "+f"(c[3])
        : "r"(a0), "r"(a1), "r"(a2), "r"(a3), "r"(b0), "r"(b1));
}
__device__ __forceinline__ void cp16(void* smem, const void* gmem) {
    unsigned saddr = (unsigned)__cvta_generic_to_shared(smem);
    asm volatile("cp.async.cg.shared.global [%0], [%1], 16;" :: "r"(saddr), "l"(gmem));
}
#define CP_COMMIT() asm volatile("cp.async.commit_group;")
#define CP_WAIT(N)  asm volatile("cp.async.wait_group %0;" :: "n"(N))
__device__ __forceinline__ int sw4(int row, int c) { return c ^ ((row >> 1) & 3); }
__device__ __forceinline__ int sw8(int row, int c) { return c ^ (row & 7); }
__device__ __forceinline__ void ldm_x4(unsigned* r, const char* p) {
    uint32_t a = (uint32_t)__cvta_generic_to_shared(p);
    asm volatile("ldmatrix.sync.aligned.m8n8.x4.shared.b16 {%0,%1,%2,%3}, [%4];"
        : "=r"(r[0]), "=r"(r[1]), "=r"(r[2]), "=r"(r[3]) : "r"(a));
}

// ---------------- fp32 -> bf16 conversion + row masks ---------------------------
__global__ __launch_bounds__(256) void cvt_kernel(
    const float* __restrict__ q, const float* __restrict__ k, const float* __restrict__ v,
    const float* __restrict__ wq, const float* __restrict__ wk, const float* __restrict__ wv)
{
    __shared__ float rs[8];
    const int z = blockIdx.y;
    const float* src; __nv_bfloat16* dst; int n;
    if (z == 0)      { src = q;  dst = g_xq; n = M_ * D_; }
    else if (z == 1) { src = k;  dst = g_xk; n = M_ * D_; }
    else if (z == 2) { src = v;  dst = g_xv; n = M_ * D_; }
    else if (z == 3) { src = wq; dst = g_wq; n = D_ * D_; }
    else if (z == 4) { src = wk; dst = g_wk; n = D_ * D_; }
    else             { src = wv; dst = g_wv; n = D_ * D_; }

    const int tid = threadIdx.x;
    int base = (blockIdx.x * 256 + tid) * 8;
    if (base >= n) return;
    float4 a = *(const float4*)&src[base];
    float4 b = *(const float4*)&src[base + 4];
    uint4 o;
    o.x = pk2(a.x, a.y); o.y = pk2(a.z, a.w);
    o.z = pk2(b.x, b.y); o.w = pk2(b.z, b.w);
    *(uint4*)&dst[base] = o;

    if (z < 2) {
        float s = a.x + a.y + a.z + a.w + b.x + b.y + b.z + b.w;
        #pragma unroll
        for (int off = 16; off; off >>= 1) s += __shfl_xor_sync(0xffffffffu, s, off);
        if ((tid & 31) == 0) rs[tid >> 5] = s;
        __syncthreads();
        float* msk = (z == 0) ? g_qmask : g_kmask;
        if (tid == 0) {
            float t = rs[0] + rs[1] + rs[2] + rs[3];
            msk[blockIdx.x * 2] = (t != 0.0f) ? 1.0f : 0.0f;
        } else if (tid == 128) {
            float t = rs[4] + rs[5] + rs[6] + rs[7];
            msk[blockIdx.x * 2 + 1] = (t != 0.0f) ? 1.0f : 0.0f;
        }
    }
}

// ---------------- fused QKV projection (bf16 MMA + ldmatrix, 3-stage cp.async) --
#define NSTG 3
#define PSTG (2 * 128 * 64)
__global__ __launch_bounds__(256) void proj_kernel(
    const float* __restrict__ bq, const float* __restrict__ bk, const float* __restrict__ bv)
{
    extern __shared__ char psm[];

    const __nv_bfloat16* X; const __nv_bfloat16* W; __nv_bfloat16* out; const float* bias;
    if (blockIdx.z == 0)      { X = g_xq; W = g_wq; out = g_Q; bias = bq; }
    else if (blockIdx.z == 1) { X = g_xk; W = g_wk; out = g_K; bias = bk; }
    else                      { X = g_xv; W = g_wv; out = g_V; bias = bv; }

    const int tid  = threadIdx.x;
    const int m0   = blockIdx.y * 128;
    const int n0   = blockIdx.x * 128;
    const int wid  = tid >> 5;
    const int lane = tid & 31;
    const int g    = lane >> 2;
    const int tig  = lane & 3;
    const int wm   = (wid >> 2) * 64;
    const int wn   = (wid & 3) * 32;
    const int sub  = lane >> 3;
    const int rin  = lane & 7;

    const int a_row = (sub & 1) * 8 + rin;
    const int a_co  = sub >> 1;
    const int b_row = (sub >> 1) * 8 + rin;
    const int b_co  = sub & 1;

    float acc[4][4][4];
    #pragma unroll
    for (int i = 0; i < 4; i++)
        #pragma unroll
        for (int j = 0; j < 4; j++)
            #pragma unroll
            for (int e = 0; e < 4; e++) acc[i][j][e] = 0.0f;

    auto load_stage = [&](int stage, int k0) {
        char* As = psm + stage * PSTG;
        char* Bs = As + 128 * 64;
        #pragma unroll
        for (int lv = 0; lv < 2; lv++) {
            int idx = tid + lv * 256;
            int row = idx >> 2;
            int c   = idx & 3;
            int cs  = sw4(row, c);
            cp16(As + row * 64 + cs * 16, &X[(size_t)(m0 + row) * D_ + k0 + c * 8]);
            cp16(Bs + row * 64 + cs * 16, &W[(size_t)(n0 + row) * D_ + k0 + c * 8]);
        }
    };

    #pragma unroll
    for (int s = 0; s < NSTG - 1; s++) { load_stage(s, s * 32); CP_COMMIT(); }

    for (int it = 0; it < 32; it++) {
        CP_WAIT(NSTG - 2);
        __syncthreads();
        if (it + NSTG - 1 < 32) load_stage((it + NSTG - 1) % NSTG, (it + NSTG - 1) * 32);
        CP_COMMIT();

        char* As = psm + (it % NSTG) * PSTG;
        char* Bs = As + 128 * 64;
        #pragma unroll
        for (int ks = 0; ks < 2; ks++) {
            unsigned af[4][4], bf[2][4];
            #pragma unroll
            for (int mi = 0; mi < 4; mi++) {
                int r = wm + mi * 16 + a_row;
                ldm_x4(af[mi], As + r * 64 + sw4(r, 2 * ks + a_co) * 16);
            }
            #pragma unroll
            for (int p = 0; p < 2; p++) {
                int r = wn + p * 16 + b_row;
                ldm_x4(bf[p], Bs + r * 64 + sw4(r, 2 * ks + b_co) * 16);
            }
            #pragma unroll
            for (int mi = 0; mi < 4; mi++)
                #pragma unroll
                for (int ni = 0; ni < 4; ni++)
                    mmabf(acc[mi][ni], af[mi][0], af[mi][1], af[mi][2], af[mi][3],
                          bf[ni >> 1][(ni & 1) * 2], bf[ni >> 1][(ni & 1) * 2 + 1]);
        }
    }

    #pragma unroll
    for (int mi = 0; mi < 4; mi++) {
        int r0 = m0 + wm + mi * 16 + g;
        #pragma unroll
        for (int ni = 0; ni < 4; ni++) {
            int cc = n0 + wn + ni * 8 + 2 * tig;
            float bb0 = bias[cc], bb1 = bias[cc + 1];
            *(unsigned*)&out[(size_t)r0 * D_ + cc] =
                pk2(fmaxf(acc[mi][ni][0] + bb0, 0.0f), fmaxf(acc[mi][ni][1] + bb1, 0.0f));
            *(unsigned*)&out[(size_t)(r0 + 8) * D_ + cc] =
                pk2(fmaxf(acc[mi][ni][2] + bb0, 0.0f), fmaxf(acc[mi][ni][3] + bb1, 0.0f));
        }
    }
}

// ---------------- V transpose ------------------------------------------------------
__global__ __launch_bounds__(256) void vt_kernel()
{
    __shared__ __nv_bfloat16 tsm[64 * 72];
    const int s0 = blockIdx.x * 64;
    const int bh = blockIdx.y;
    const int b  = bh >> 4;
    const int h  = bh & 15;
    const int tid = threadIdx.x;

    #pragma unroll
    for (int lv = 0; lv < 2; lv++) {
        int idx = tid + lv * 256;
        int r = idx >> 3;
        int c = idx & 7;
        *(uint4*)&tsm[r * 72 + c * 8] =
            *(const uint4*)&g_V[(size_t)(b * S_ + s0 + r) * D_ + h * DH_ + c * 8];
    }
    __syncthreads();

    #pragma unroll
    for (int i = 0; i < 2; i++) {
        int d = (tid & 63);
        int c = (tid >> 6) + i * 4;
        uint4 o;
        unsigned* po = (unsigned*)&o;
        #pragma unroll
        for (int jj = 0; jj < 4; jj++) {
            unsigned short lo = *(unsigned short*)&tsm[(c * 8 + jj * 2)     * 72 + d];
            unsigned short hi = *(unsigned short*)&tsm[(c * 8 + jj * 2 + 1) * 72 + d];
            po[jj] = (unsigned)lo | ((unsigned)hi << 16);
        }
        *(uint4*)&g_Vt[(size_t)bh * DH_ * S_ + (size_t)d * S_ + s0 + c * 8] = o;
    }
}

// ---------------- causal flash attention ----------------------------------------
// Fast path for interior/all-valid tiles: no mask math at all.
#define AQ_OFF  0
#define AK_OFF  (128 * 128)
#define AV_OFF  (AK_OFF + 2 * 64 * 128)
#define AM_OFF  (AV_OFF + 2 * 64 * 128)
#define ATTN_SMEM (AM_OFF + 2 * 64 * 4)
#define CS 0.1803368801f   // 0.125 * log2(e)
__global__ __launch_bounds__(256) void attn_kernel()
{
    extern __shared__ char sm[];
    char*  qp  = sm + AQ_OFF;
    char*  Kst = sm + AK_OFF;
    char*  Vst = sm + AV_OFF;
    float* kms = (float*)(sm + AM_OFF);

    const int qt   = gridDim.x - 1 - blockIdx.x;
    const int qb0  = qt * 128;
    const int h    = blockIdx.y;
    const int b    = blockIdx.z;
    const int tid  = threadIdx.x;
    const int wid  = tid >> 5;
    const int lane = tid & 31;
    const int g    = lane >> 2;
    const int tig  = lane & 3;
    const int rb   = wid * 16;
    const int sub  = lane >> 3;
    const int rin  = lane & 7;

    const int a_row = (sub & 1) * 8 + rin;
    const int a_co  = sub >> 1;
    const int b_row = (sub >> 1) * 8 + rin;
    const int b_co  = sub & 1;

    const int ntile = (qb0 >> 6) + 2;
    const __nv_bfloat16* Vtg = g_Vt + (size_t)(b * H_ + h) * DH_ * S_;

    #pragma unroll
    for (int lv = 0; lv < 4; lv++) {
        int idx = tid + lv * 256;
        int r = idx >> 3;
        int c = idx & 7;
        cp16(qp + r * 128 + sw8(r, c) * 16,
             &g_Q[(size_t)(b * S_ + qb0 + r) * D_ + h * DH_ + c * 8]);
    }
    CP_COMMIT();
    {
        #pragma unroll
        for (int lv = 0; lv < 2; lv++) {
            int idx = tid + lv * 256;
            int r = idx >> 3;
            int c = idx & 7;
            cp16(Kst + r * 128 + sw8(r, c) * 16,
                 &g_K[(size_t)(b * S_ + r) * D_ + h * DH_ + c * 8]);
            cp16(Vst + r * 128 + sw8(r, c) * 16, &Vtg[(size_t)r * S_ + c * 8]);
        }
        if (tid < 16) cp16(&kms[tid * 4], &g_kmask[b * S_ + tid * 4]);
    }
    CP_COMMIT();

    CP_WAIT(1);
    __syncthreads();

    unsigned qa[4][4];
    #pragma unroll
    for (int ks = 0; ks < 4; ks++) {
        int r = rb + a_row;
        ldm_x4(qa[ks], qp + r * 128 + sw8(r, 2 * ks + a_co) * 16);
    }

    float oacc[8][4];
    #pragma unroll
    for (int ni = 0; ni < 8; ni++)
        #pragma unroll
        for (int e = 0; e < 4; e++) oacc[ni][e] = 0.0f;
    float mrow0 = -1e30f, mrow1 = -1e30f, lrow0 = 0.0f, lrow1 = 0.0f;

    const int row0 = qb0 + rb + g;
    const int row1 = row0 + 8;
    const int rmax = qb0 + rb + 15;

    for (int kt = 0; kt < ntile; kt++) {
        const int cur = kt & 1;
        const int s0  = kt * 64;

        CP_WAIT(0);
        __syncthreads();

        if (kt + 1 < ntile) {
            const int nxt = cur ^ 1;
            const int sn  = (kt + 1) * 64;
            char* Ks = Kst + nxt * 64 * 128;
            char* Vs = Vst + nxt * 64 * 128;
            #pragma unroll
            for (int lv = 0; lv < 2; lv++) {
                int idx = tid + lv * 256;
                int r = idx >> 3;
                int c = idx & 7;
                cp16(Ks + r * 128 + sw8(r, c) * 16,
                     &g_K[(size_t)(b * S_ + sn + r) * D_ + h * DH_ + c * 8]);
                cp16(Vs + r * 128 + sw8(r, c) * 16, &Vtg[(size_t)r * S_ + sn + c * 8]);
            }
            if (tid < 16) cp16(&kms[nxt * 64 + tid * 4], &g_kmask[b * S_ + sn + tid * 4]);
        }
        CP_COMMIT();

        if (s0 > rmax) continue;

        char*  Ksm = Kst + cur * 64 * 128;
        char*  Vsm = Vst + cur * 64 * 128;
        float* kmc = kms + cur * 64;

        // tile classification
        float kv0 = kmc[lane], kv1 = kmc[lane + 32];
        bool okk = (kv0 != 0.0f) && (kv1 != 0.0f);
        bool allvalid = (__ballot_sync(0xffffffffu, okk) == 0xffffffffu);
        bool interior = (s0 + 63 <= qb0 + rb);

        // S = Q K^T (16 x 64 per warp)
        float sc[8][4];
        #pragma unroll
        for (int ni = 0; ni < 8; ni++)
            #pragma unroll
            for (int e = 0; e < 4; e++) sc[ni][e] = 0.0f;

        #pragma unroll
        for (int ks = 0; ks < 4; ks++) {
            #pragma unroll
            for (int p = 0; p < 4; p++) {
                unsigned kf[4];
                int r = p * 16 + b_row;
                ldm_x4(kf, Ksm + r * 128 + sw8(r, 2 * ks + b_co) * 16);
                mmabf(sc[2 * p],     qa[ks][0], qa[ks][1], qa[ks][2], qa[ks][3], kf[0], kf[1]);
                mmabf(sc[2 * p + 1], qa[ks][0], qa[ks][1], qa[ks][2], qa[ks][3], kf[2], kf[3]);
            }
        }

        // scale (+ masks only when needed)
        float vm0 = -1e30f, vm1 = -1e30f;
        if (interior && allvalid) {
            #pragma unroll
            for (int ni = 0; ni < 8; ni++) {
                sc[ni][0] *= CS; sc[ni][1] *= CS; sc[ni][2] *= CS; sc[ni][3] *= CS;
                vm0 = fmaxf(vm0, fmaxf(sc[ni][0], sc[ni][1]));
                vm1 = fmaxf(vm1, fmaxf(sc[ni][2], sc[ni][3]));
            }
        } else {
            #pragma unroll
            for (int ni = 0; ni < 8; ni++) {
                #pragma unroll
                for (int e = 0; e < 2; e++) {
                    int cl = ni * 8 + 2 * tig + e;
                    int sg = s0 + cl;
                    bool km = (kmc[cl] != 0.0f);
                    float v0 = sc[ni][e] * CS;
                    float v1 = sc[ni][2 + e] * CS;
                    v0 = (sg > row0 || !km) ? -1e30f : v0;
                    v1 = (sg > row1 || !km) ? -1e30f : v1;
                    sc[ni][e] = v0; sc[ni][2 + e] = v1;
                    vm0 = fmaxf(vm0, v0); vm1 = fmaxf(vm1, v1);
                }
            }
        }
        vm0 = fmaxf(vm0, __shfl_xor_sync(0xffffffffu, vm0, 1));
        vm0 = fmaxf(vm0, __shfl_xor_sync(0xffffffffu, vm0, 2));
        vm1 = fmaxf(vm1, __shfl_xor_sync(0xffffffffu, vm1, 1));
        vm1 = fmaxf(vm1, __shfl_xor_sync(0xffffffffu, vm1, 2));

        float mn0 = fmaxf(mrow0, vm0), mn1 = fmaxf(mrow1, vm1);
        float al0 = ex2(mrow0 - mn0), al1 = ex2(mrow1 - mn1);

        // P in registers (A-operand fragment layout)
        unsigned pp[8][2];
        float ps0 = 0.0f, ps1 = 0.0f;
        #pragma unroll
        for (int ni = 0; ni < 8; ni++) {
            float p00 = ex2(sc[ni][0] - mn0);
            float p01 = ex2(sc[ni][1] - mn0);
            float p10 = ex2(sc[ni][2] - mn1);
            float p11 = ex2(sc[ni][3] - mn1);
            ps0 += p00 + p01; ps1 += p10 + p11;
            pp[ni][0] = pk2(p00, p01);
            pp[ni][1] = pk2(p10, p11);
        }
        ps0 += __shfl_xor_sync(0xffffffffu, ps0, 1);
        ps0 += __shfl_xor_sync(0xffffffffu, ps0, 2);
        ps1 += __shfl_xor_sync(0xffffffffu, ps1, 1);
        ps1 += __shfl_xor_sync(0xffffffffu, ps1, 2);

        lrow0 = lrow0 * al0 + ps0;
        lrow1 = lrow1 * al1 + ps1;
        mrow0 = mn0; mrow1 = mn1;
        #pragma unroll
        for (int ni = 0; ni < 8; ni++) {
            oacc[ni][0] *= al0; oacc[ni][1] *= al0;
            oacc[ni][2] *= al1; oacc[ni][3] *= al1;
        }

        // O += P @ V
        #pragma unroll
        for (int ks = 0; ks < 4; ks++) {
            unsigned pa0 = pp[2 * ks][0];
            unsigned pa1 = pp[2 * ks][1];
            unsigned pa2 = pp[2 * ks + 1][0];
            unsigned pa3 = pp[2 * ks + 1][1];
            #pragma unroll
            for (int p = 0; p < 4; p++) {
                unsigned vf[4];
                int r = p * 16 + b_row;
                ldm_x4(vf, Vsm + r * 128 + sw8(r, 2 * ks + b_co) * 16);
                mmabf(oacc[2 * p],     pa0, pa1, pa2, pa3, vf[0], vf[1]);
                mmabf(oacc[2 * p + 1], pa0, pa1, pa2, pa3, vf[2], vf[3]);
            }
        }
    }

    float qm0 = g_qmask[b * S_ + row0];
    float qm1 = g_qmask[b * S_ + row1];
    float inv0 = qm0 / lrow0;
    float inv1 = qm1 / lrow1;
    #pragma unroll
    for (int ni = 0; ni < 8; ni++) {
        int cc = h * DH_ + ni * 8 + 2 * tig;
        float2 v0, v1;
        v0.x = oacc[ni][0] * inv0; v0.y = oacc[ni][1] * inv0;
        v1.x = oacc[ni][2] * inv1; v1.y = oacc[ni][3] * inv1;
        *(float2*)&g_O[(size_t)(b * S_ + row0) * D_ + cc] = v0;
        *(float2*)&g_O[(size_t)(b * S_ + row1) * D_ + cc] = v1;
    }
}

// ---------------- residual + layernorm ------------------------------------------
__global__ __launch_bounds__(256) void ln_kernel(
    const float* __restrict__ qin, const float* __restrict__ gamma,
    const float* __restrict__ beta, float* __restrict__ out)
{
    __shared__ float red[8];
    __shared__ float red2[8];
    const int row = blockIdx.x;
    const int tid = threadIdx.x;
    size_t base = (size_t)row * D_ + tid * 4;

    float4 o = *(const float4*)&g_O[base];
    float4 q = *(const float4*)&qin[base];
    float x0 = o.x + q.x, x1 = o.y + q.y, x2 = o.z + q.z, x3 = o.w + q.w;

    float s = x0 + x1 + x2 + x3;
    #pragma unroll
    for (int off = 16; off; off >>= 1) s += __shfl_xor_sync(0xffffffffu, s, off);
    if ((tid & 31) == 0) red[tid >> 5] = s;
    __syncthreads();
    float tot = red[0] + red[1] + red[2] + red[3] + red[4] + red[5] + red[6] + red[7];
    float mean = tot * (1.0f / 1024.0f);

    float d0 = x0 - mean, d1 = x1 - mean, d2 = x2 - mean, d3 = x3 - mean;
    float sq = d0 * d0 + d1 * d1 + d2 * d2 + d3 * d3;
    #pragma unroll
    for (int off = 16; off; off >>= 1) sq += __shfl_xor_sync(0xffffffffu, sq, off);
    if ((tid & 31) == 0) red2[tid >> 5] = sq;
    __syncthreads();
    float ssq = red2[0] + red2[1] + red2[2] + red2[3] + red2[4] + red2[5] + red2[6] + red2[7];
    float stdv = sqrtf(ssq / 1023.0f);
    float inv = 1.0f / (stdv + 1e-8f);

    float4 gg = *(const float4*)&gamma[tid * 4];
    float4 be = *(const float4*)&beta[tid * 4];
    float4 y;
    y.x = gg.x * d0 * inv + be.x;
    y.y = gg.y * d1 * inv + be.y;
    y.z = gg.z * d2 * inv + be.z;
    y.w = gg.w * d3 * inv + be.w;
    *(float4*)&out[base] = y;
}

// ---------------- launch -----------------------------------------------------------
extern "C" void kernel_launch(void* const* d_in, const int* in_sizes, int n_in,
                              void* d_out, int out_size)
{
    const float* queries = (const float*)d_in[0];
    const float* keys    = (const float*)d_in[1];
    const float* values  = (const float*)d_in[2];
    const float* Wq      = (const float*)d_in[3];
    const float* bq      = (const float*)d_in[4];
    const float* Wk      = (const float*)d_in[5];
    const float* bk      = (const float*)d_in[6];
    const float* Wv      = (const float*)d_in[7];
    const float* bv      = (const float*)d_in[8];
    const float* gamma   = (const float*)d_in[9];
    const float* beta    = (const float*)d_in[10];
    float* out = (float*)d_out;

    const int proj_smem = NSTG * PSTG;
    cudaFuncSetAttribute(proj_kernel, cudaFuncAttributeMaxDynamicSharedMemorySize, proj_smem);
    cudaFuncSetAttribute(attn_kernel, cudaFuncAttributeMaxDynamicSharedMemorySize, ATTN_SMEM);

    cvt_kernel<<<dim3(2048, 6), 256>>>(queries, keys, values, Wq, Wk, Wv);
    proj_kernel<<<dim3(8, 32, 3), 256, proj_smem>>>(bq, bk, bv);
    vt_kernel<<<dim3(32, 32), 256>>>();
    attn_kernel<<<dim3(16, 16, 2), 256, ATTN_SMEM>>>();
    ln_kernel<<<M_, 256>>>(queries, gamma, beta, out);
}